// round 11
// baseline (speedup 1.0000x reference)
#include <cuda_runtime.h>
#include <cuda_bf16.h>
#include <cstdint>

#define Bz 16
#define Nn 1024
#define Cc 768
#define Dd 384

// All GEMM operands stored as [row][2K] bf16: per 32-k block, 64 elems = [hi32|lo32]
#define LD_X   1536   // 2*768
#define LD_D   768    // 2*384
#define LD_T   2048   // 2*1024

#define TILE_B  16384            // 128 rows x 128B
#define STAGE_B 32768            // A tile + B tile
#define NSTAGE  3
#define SMEM_DYN (NSTAGE*STAGE_B + 128)

// ---------------- static scratch ----------------
__device__ __align__(16) __nv_bfloat16 g_xA2 [(size_t)Bz*Nn*LD_X];
__device__ __align__(16) __nv_bfloat16 g_wB2 [(size_t)3*Dd*LD_X];
__device__              float          g_bias[3*Dd];
__device__ __align__(16) __nv_bfloat16 g_th2 [(size_t)Bz*Nn*LD_D];
__device__ __align__(16) __nv_bfloat16 g_ph2 [(size_t)Bz*Nn*LD_D];
__device__ __align__(16) __nv_bfloat16 g_g2  [(size_t)Bz*Dd*LD_T];
__device__ __align__(16) float         g_attn[(size_t)Bz*Nn*Nn];
__device__ __align__(16) __nv_bfloat16 g_at2 [(size_t)Bz*Nn*LD_T];
__device__ __align__(16) __nv_bfloat16 g_od2 [(size_t)Bz*Nn*LD_D];
__device__ __align__(16) __nv_bfloat16 g_wo2 [(size_t)Cc*LD_D];

// ---------------- helpers ----------------
__device__ __forceinline__ uint32_t smem_u32(const void* p){
    uint32_t a;
    asm("{ .reg .u64 t; cvta.to.shared.u64 t, %1; cvt.u32.u64 %0, t; }" : "=r"(a) : "l"(p));
    return a;
}
__device__ __forceinline__ void cpa16(uint32_t dst, const void* src){
    asm volatile("cp.async.cg.shared.global [%0], [%1], 16;" :: "r"(dst), "l"(src));
}
#define CP_COMMIT() asm volatile("cp.async.commit_group;" ::: "memory")
#define CP_WAIT(N)  asm volatile("cp.async.wait_group %0;" :: "n"(N) : "memory")

__device__ __forceinline__ void ldsm4(uint32_t (&d)[4], uint32_t a){
    asm volatile("ldmatrix.sync.aligned.m8n8.x4.shared.b16 {%0,%1,%2,%3}, [%4];"
        : "=r"(d[0]), "=r"(d[1]), "=r"(d[2]), "=r"(d[3]) : "r"(a));
}
__device__ __forceinline__ void mma16816(float (&c)[4], const uint32_t (&a)[4],
                                         uint32_t b0, uint32_t b1){
    asm volatile("mma.sync.aligned.m16n8k16.row.col.f32.bf16.bf16.f32 "
        "{%0,%1,%2,%3}, {%4,%5,%6,%7}, {%8,%9}, {%0,%1,%2,%3};"
        : "+f"(c[0]), "+f"(c[1]), "+f"(c[2]), "+f"(c[3])
        : "r"(a[0]), "r"(a[1]), "r"(a[2]), "r"(a[3]), "r"(b0), "r"(b1));
}

__device__ __forceinline__ uint32_t bf2u(__nv_bfloat16 a, __nv_bfloat16 b){
    return (uint32_t)__bfloat16_as_ushort(a) | ((uint32_t)__bfloat16_as_ushort(b) << 16);
}
__device__ __forceinline__ void split_bf(float v, __nv_bfloat16& h, __nv_bfloat16& l){
    h = __float2bfloat16(v);
    l = __float2bfloat16(v - __bfloat162float(h));
}
__device__ __forceinline__ void store_hl(__nv_bfloat16* base, int d, float v0, float v1){
    __nv_bfloat16 h0,l0,h1,l1;
    split_bf(v0,h0,l0); split_bf(v1,h1,l1);
    __nv_bfloat16* p = base + ((d >> 5) << 6) + (d & 31);
    *(uint32_t*)(p)      = bf2u(h0,h1);
    *(uint32_t*)(p + 32) = bf2u(l0,l1);
}

// ---------------- 3-term split HMMA GEMM core ----------------
// C ~= Ahi*Bhi + Ahi*Blo + Alo*Bhi per 32-k block from one 32KB stage.
// CTA tile 128x128, 8 warps (2x4), warp tile 64x32.
__device__ __forceinline__ void gemm3(
    const __nv_bfloat16* __restrict__ A, int ldA,
    const __nv_bfloat16* __restrict__ B, int ldB,
    int nkb, char* sm, float acc[4][4][4])
{
    const int tid  = threadIdx.x;
    const int lane = tid & 31;
    const int w    = tid >> 5;
    const int wr   = w >> 2, wc = w & 3;
    const uint32_t sbase = (smem_u32(sm) + 127u) & ~127u;

    int goA[4], goB[4], smo[4];
#pragma unroll
    for (int i = 0; i < 4; i++){
        int idx = i * 256 + tid;
        int rr = idx >> 3, cc = idx & 7;
        goA[i] = rr * ldA + cc * 8;
        goB[i] = rr * ldB + cc * 8;
        smo[i] = rr * 128 + ((cc * 16) ^ ((rr & 7) << 4));
    }

    const int xorv = (lane & 7) << 4;
    int arow[4];
#pragma unroll
    for (int mi = 0; mi < 4; mi++) arow[mi] = (wr * 64 + mi * 16 + (lane & 15)) * 128;
    // B ldsm4: lanes 0-7: rows +0..7 khalf0; 8-15: rows +0..7 khalf1;
    //          16-23: rows +8..15 khalf0; 24-31: rows +8..15 khalf1
    const int brow4 = (wc * 32 + ((lane >> 4) << 3) + (lane & 7)) * 128;
    const int acs = (lane & 16);
    const int bcs = (lane & 8) << 1;

#pragma unroll
    for (int mi = 0; mi < 4; mi++)
#pragma unroll
        for (int ni = 0; ni < 4; ni++)
#pragma unroll
            for (int q = 0; q < 4; q++) acc[mi][ni][q] = 0.f;

    // prologue: issue chunks 0,1
#pragma unroll
    for (int pc = 0; pc < 2; pc++){
        const uint32_t s = sbase + pc * STAGE_B;
        const __nv_bfloat16* Ak = A + pc * 64;
        const __nv_bfloat16* Bk = B + pc * 64;
#pragma unroll
        for (int i = 0; i < 4; i++) cpa16(s + smo[i], Ak + goA[i]);
#pragma unroll
        for (int i = 0; i < 4; i++) cpa16(s + TILE_B + smo[i], Bk + goB[i]);
        CP_COMMIT();
    }

    int stg = 0;
    for (int c = 0; c < nkb; ++c){
        if (c + 1 < nkb) { CP_WAIT(1); } else { CP_WAIT(0); }
        __syncthreads();

        // issue chunk c+2 NOW (stage (c+2)%3 was read at c-1; barrier above protects it)
        if (c + 2 < nkb){
            const int ns = (stg + 2 >= NSTAGE) ? stg + 2 - NSTAGE : stg + 2;
            const uint32_t s = sbase + ns * STAGE_B;
            const __nv_bfloat16* Ak = A + (c + 2) * 64;
            const __nv_bfloat16* Bk = B + (c + 2) * 64;
#pragma unroll
            for (int i = 0; i < 4; i++) cpa16(s + smo[i], Ak + goA[i]);
#pragma unroll
            for (int i = 0; i < 4; i++) cpa16(s + TILE_B + smo[i], Bk + goB[i]);
            CP_COMMIT();
        }

        const uint32_t sA = sbase + stg * STAGE_B;
        const uint32_t sB = sA + TILE_B;
#pragma unroll
        for (int ks = 0; ks < 2; ks++){
            const int chA = ((ks << 5) | acs);
            const int chB = ((ks << 5) | bcs);
            uint32_t ahi[4][4];
            uint32_t bh[2][4];
            // B hi: 2 x ldsm4 covers all 4 n8-blocks x 2 k-halves
#pragma unroll
            for (int p = 0; p < 2; p++)
                ldsm4(bh[p], sB + brow4 + p * 2048 + (chB ^ xorv));
#pragma unroll
            for (int mi = 0; mi < 4; mi++)
                ldsm4(ahi[mi], sA + arow[mi] + (chA ^ xorv));
            // pass 1: hi*hi
#pragma unroll
            for (int ni = 0; ni < 4; ni++)
#pragma unroll
                for (int mi = 0; mi < 4; mi++)
                    mma16816(acc[mi][ni], ahi[mi], bh[ni >> 1][(ni & 1) * 2], bh[ni >> 1][(ni & 1) * 2 + 1]);
            // pass 2: hi*lo
            {
                uint32_t bl[2][4];
#pragma unroll
                for (int p = 0; p < 2; p++)
                    ldsm4(bl[p], sB + brow4 + p * 2048 + ((chB | 64) ^ xorv));
#pragma unroll
                for (int ni = 0; ni < 4; ni++)
#pragma unroll
                    for (int mi = 0; mi < 4; mi++)
                        mma16816(acc[mi][ni], ahi[mi], bl[ni >> 1][(ni & 1) * 2], bl[ni >> 1][(ni & 1) * 2 + 1]);
            }
            // pass 3: lo*hi (reuse ahi registers for alo)
#pragma unroll
            for (int mi = 0; mi < 4; mi++)
                ldsm4(ahi[mi], sA + arow[mi] + ((chA | 64) ^ xorv));
#pragma unroll
            for (int ni = 0; ni < 4; ni++)
#pragma unroll
                for (int mi = 0; mi < 4; mi++)
                    mma16816(acc[mi][ni], ahi[mi], bh[ni >> 1][(ni & 1) * 2], bh[ni >> 1][(ni & 1) * 2 + 1]);
        }
        stg = (stg + 1 == NSTAGE) ? 0 : stg + 1;
    }
}

// ---------------- conversion kernels ----------------
__global__ __launch_bounds__(256) void k_cvt_x(const float* __restrict__ x){
    const int idx = blockIdx.x * 256 + threadIdx.x;
    const int m = idx / 192, kq = idx % 192;
    const int k = kq * 4;
    float4 v = *(const float4*)(x + (size_t)m * Cc + k);
    __nv_bfloat16 h0,h1,h2,h3,l0,l1,l2,l3;
    split_bf(v.x,h0,l0); split_bf(v.y,h1,l1); split_bf(v.z,h2,l2); split_bf(v.w,h3,l3);
    __nv_bfloat16* p = g_xA2 + (size_t)m * LD_X + ((k >> 5) << 6) + (k & 31);
    uint2 uh; uh.x = bf2u(h0,h1); uh.y = bf2u(h2,h3);
    uint2 ul; ul.x = bf2u(l0,l1); ul.y = bf2u(l2,l3);
    *(uint2*)(p)      = uh;
    *(uint2*)(p + 32) = ul;
}

__global__ __launch_bounds__(256) void k_cvt_w(
    const float* __restrict__ Wt, const float* __restrict__ bt,
    const float* __restrict__ Wp, const float* __restrict__ bp,
    const float* __restrict__ Wg, const float* __restrict__ bg)
{
    const int idx = blockIdx.x * 256 + threadIdx.x;
    const int n = idx / 192, kq = idx % 192;
    const int which = n / Dd, d = n % Dd;
    const int k = kq * 4;
    const float* W = (which == 0) ? Wt : (which == 1) ? Wp : Wg;
    __nv_bfloat16 h[4], l[4];
#pragma unroll
    for (int t = 0; t < 4; t++)
        split_bf(W[(size_t)(k + t) * Dd + d], h[t], l[t]);
    __nv_bfloat16* p = g_wB2 + (size_t)n * LD_X + ((k >> 5) << 6) + (k & 31);
    uint2 uh; uh.x = bf2u(h[0],h[1]); uh.y = bf2u(h[2],h[3]);
    uint2 ul; ul.x = bf2u(l[0],l[1]); ul.y = bf2u(l[2],l[3]);
    *(uint2*)(p)      = uh;
    *(uint2*)(p + 32) = ul;
    if (kq == 0){
        const float* bb = (which == 0) ? bt : (which == 1) ? bp : bg;
        g_bias[n] = bb[d];
    }
}

__global__ __launch_bounds__(256) void k_cvt_wo(const float* __restrict__ Wo){
    const int idx = blockIdx.x * 256 + threadIdx.x;
    const int n = idx / 96, kq = idx % 96;
    const int k = kq * 4;
    __nv_bfloat16 h[4], l[4];
#pragma unroll
    for (int t = 0; t < 4; t++)
        split_bf(Wo[(size_t)(k + t) * Cc + n], h[t], l[t]);
    __nv_bfloat16* p = g_wo2 + (size_t)n * LD_D + ((k >> 5) << 6) + (k & 31);
    uint2 uh; uh.x = bf2u(h[0],h[1]); uh.y = bf2u(h[2],h[3]);
    uint2 ul; ul.x = bf2u(l[0],l[1]); ul.y = bf2u(l[2],l[3]);
    *(uint2*)(p)      = uh;
    *(uint2*)(p + 32) = ul;
}

// ---------------- GEMM 1: projections ----------------
__global__ __launch_bounds__(256, 2) void k_proj_t(){
    extern __shared__ char sm[];
    const int lane = threadIdx.x & 31, w = threadIdx.x >> 5;
    const int wr = w >> 2, wc = w & 3;
    const int n0 = blockIdx.x * 128, m0 = blockIdx.y * 128;
    float acc[4][4][4];
    gemm3(g_xA2 + (size_t)m0 * LD_X, LD_X,
          g_wB2 + (size_t)n0 * LD_X, LD_X, Cc / 32, sm, acc);

    const int seg = n0 / Dd, d0 = n0 % Dd;
#pragma unroll
    for (int mi = 0; mi < 4; mi++)
#pragma unroll
    for (int ni = 0; ni < 4; ni++)
#pragma unroll
    for (int h = 0; h < 2; h++){
        const int r   = wr * 64 + mi * 16 + (lane >> 2) + h * 8;
        const int col = wc * 32 + ni * 8 + (lane & 3) * 2;
        const int mrow = m0 + r;
        const int ng = n0 + col;
        const float v0 = acc[mi][ni][h * 2]     + g_bias[ng];
        const float v1 = acc[mi][ni][h * 2 + 1] + g_bias[ng + 1];
        const int d = d0 + col;
        if (seg == 0){
            store_hl(g_th2 + (size_t)mrow * LD_D, d, v0, v1);
        } else if (seg == 1){
            store_hl(g_ph2 + (size_t)mrow * LD_D, d, v0, v1);
        } else {
            const int b = mrow >> 10, ml = mrow & 1023;
            const int off = ((ml >> 5) << 6) + (ml & 31);
            __nv_bfloat16 h0, l0, h1, l1;
            split_bf(v0, h0, l0); split_bf(v1, h1, l1);
            __nv_bfloat16* q0 = g_g2 + (size_t)(b * Dd + d)     * LD_T + off;
            __nv_bfloat16* q1 = g_g2 + (size_t)(b * Dd + d + 1) * LD_T + off;
            q0[0] = h0; q0[32] = l0;
            q1[0] = h1; q1[32] = l1;
        }
    }
}

// ---------------- GEMM 2: scores = (theta @ phi^T) * adj ----------------
__global__ __launch_bounds__(256, 2) void k_score_t(const float* __restrict__ adj){
    extern __shared__ char sm[];
    const int lane = threadIdx.x & 31, w = threadIdx.x >> 5;
    const int wr = w >> 2, wc = w & 3;
    const int b = blockIdx.z, j0 = blockIdx.x * 128, i0 = blockIdx.y * 128;
    float acc[4][4][4];
    gemm3(g_th2 + (size_t)(b * Nn + i0) * LD_D, LD_D,
          g_ph2 + (size_t)(b * Nn + j0) * LD_D, LD_D, Dd / 32, sm, acc);

#pragma unroll
    for (int mi = 0; mi < 4; mi++)
#pragma unroll
    for (int ni = 0; ni < 4; ni++)
#pragma unroll
    for (int h = 0; h < 2; h++){
        const int i = i0 + wr * 64 + mi * 16 + (lane >> 2) + h * 8;
        const int j = j0 + wc * 32 + ni * 8 + (lane & 3) * 2;
        const size_t idx = ((size_t)b * Nn + i) * Nn + j;
        const float2 a2 = *(const float2*)(adj + idx);
        float2 o;
        o.x = acc[mi][ni][h * 2]     * a2.x;
        o.y = acc[mi][ni][h * 2 + 1] * a2.y;
        *(float2*)(g_attn + idx) = o;
    }
}

// ---------------- softmax + hi|lo split ----------------
__global__ __launch_bounds__(256) void k_softmax2(){
    const size_t row = blockIdx.x;
    const float4 v = ((const float4*)(g_attn + row * Nn))[threadIdx.x];

    float m = fmaxf(fmaxf(v.x, v.y), fmaxf(v.z, v.w));
#pragma unroll
    for (int o = 16; o; o >>= 1) m = fmaxf(m, __shfl_xor_sync(0xffffffffu, m, o));
    __shared__ float red[8];
    const int warp = threadIdx.x >> 5;
    if ((threadIdx.x & 31) == 0) red[warp] = m;
    __syncthreads();
    float bm = red[0];
#pragma unroll
    for (int i = 1; i < 8; i++) bm = fmaxf(bm, red[i]);
    __syncthreads();

    float4 e;
    e.x = __expf(v.x - bm); e.y = __expf(v.y - bm);
    e.z = __expf(v.z - bm); e.w = __expf(v.w - bm);
    float s = e.x + e.y + e.z + e.w;
#pragma unroll
    for (int o = 16; o; o >>= 1) s += __shfl_xor_sync(0xffffffffu, s, o);
    if ((threadIdx.x & 31) == 0) red[warp] = s;
    __syncthreads();
    float tot = red[0];
#pragma unroll
    for (int i = 1; i < 8; i++) tot += red[i];
    const float inv = 1.0f / tot;
    e.x *= inv; e.y *= inv; e.z *= inv; e.w *= inv;

    const int t = threadIdx.x * 4;
    __nv_bfloat16 h0,h1,h2,h3,l0,l1,l2,l3;
    split_bf(e.x,h0,l0); split_bf(e.y,h1,l1); split_bf(e.z,h2,l2); split_bf(e.w,h3,l3);
    __nv_bfloat16* p = g_at2 + row * LD_T + ((t >> 5) << 6) + (t & 31);
    uint2 uh; uh.x = bf2u(h0,h1); uh.y = bf2u(h2,h3);
    uint2 ul; ul.x = bf2u(l0,l1); ul.y = bf2u(l2,l3);
    *(uint2*)(p)      = uh;
    *(uint2*)(p + 32) = ul;
}

// ---------------- GEMM 3: attn @ g ----------------
__global__ __launch_bounds__(256, 2) void k_av_t(){
    extern __shared__ char sm[];
    const int lane = threadIdx.x & 31, w = threadIdx.x >> 5;
    const int wr = w >> 2, wc = w & 3;
    const int b = blockIdx.z, n0 = blockIdx.x * 128, i0 = blockIdx.y * 128;
    float acc[4][4][4];
    gemm3(g_at2 + (size_t)(b * Nn + i0) * LD_T, LD_T,
          g_g2  + (size_t)(b * Dd + n0) * LD_T, LD_T, Nn / 32, sm, acc);

#pragma unroll
    for (int mi = 0; mi < 4; mi++)
#pragma unroll
    for (int ni = 0; ni < 4; ni++)
#pragma unroll
    for (int h = 0; h < 2; h++){
        const int r   = wr * 64 + mi * 16 + (lane >> 2) + h * 8;
        const int col = wc * 32 + ni * 8 + (lane & 3) * 2;
        const int mrow = b * Nn + i0 + r;
        store_hl(g_od2 + (size_t)mrow * LD_D, n0 + col,
                 acc[mi][ni][h * 2], acc[mi][ni][h * 2 + 1]);
    }
}

// ---------------- GEMM 4: output + bias + residual ----------------
__global__ __launch_bounds__(256, 2) void k_out_t(
    const float* __restrict__ x, const float* __restrict__ bo, float* __restrict__ out)
{
    extern __shared__ char sm[];
    const int lane = threadIdx.x & 31, w = threadIdx.x >> 5;
    const int wr = w >> 2, wc = w & 3;
    const int n0 = blockIdx.x * 128, m0 = blockIdx.y * 128;
    float acc[4][4][4];
    gemm3(g_od2 + (size_t)m0 * LD_D, LD_D,
          g_wo2 + (size_t)n0 * LD_D, LD_D, Dd / 32, sm, acc);

#pragma unroll
    for (int mi = 0; mi < 4; mi++)
#pragma unroll
    for (int ni = 0; ni < 4; ni++)
#pragma unroll
    for (int h = 0; h < 2; h++){
        const int row = m0 + wr * 64 + mi * 16 + (lane >> 2) + h * 8;
        const int cg  = n0 + wc * 32 + ni * 8 + (lane & 3) * 2;
        const size_t idx = (size_t)row * Cc + cg;
        const float2 xv = *(const float2*)(x + idx);
        const float2 bv = *(const float2*)(bo + cg);
        float2 o;
        o.x = acc[mi][ni][h * 2]     + bv.x + xv.x;
        o.y = acc[mi][ni][h * 2 + 1] + bv.y + xv.y;
        *(float2*)(out + idx) = o;
    }
}

// ---------------------------------------------------------------------------
extern "C" void kernel_launch(void* const* d_in, const int* in_sizes, int n_in,
                              void* d_out, int out_size)
{
    const float* x  = (const float*)d_in[0];
    const float* adj = (const float*)d_in[1];
    const float* Wt = (const float*)d_in[2];
    const float* bt = (const float*)d_in[3];
    const float* Wp = (const float*)d_in[4];
    const float* bp = (const float*)d_in[5];
    const float* Wg = (const float*)d_in[6];
    const float* bg = (const float*)d_in[7];
    const float* Wo = (const float*)d_in[8];
    const float* bo = (const float*)d_in[9];
    float* out = (float*)d_out;

    static bool attr_done = false;
    if (!attr_done){
        cudaFuncSetAttribute(k_proj_t,  cudaFuncAttributeMaxDynamicSharedMemorySize, SMEM_DYN);
        cudaFuncSetAttribute(k_score_t, cudaFuncAttributeMaxDynamicSharedMemorySize, SMEM_DYN);
        cudaFuncSetAttribute(k_av_t,    cudaFuncAttributeMaxDynamicSharedMemorySize, SMEM_DYN);
        cudaFuncSetAttribute(k_out_t,   cudaFuncAttributeMaxDynamicSharedMemorySize, SMEM_DYN);
        attr_done = true;
    }

    k_cvt_x <<<(Bz * Nn * 192) / 256, 256>>>(x);
    k_cvt_w <<<(3 * Dd * 192) / 256, 256>>>(Wt, bt, Wp, bp, Wg, bg);
    k_cvt_wo<<<(Cc * 96) / 256, 256>>>(Wo);

    k_proj_t <<<dim3(9, 128),   256, SMEM_DYN>>>();
    k_score_t<<<dim3(8, 8, Bz), 256, SMEM_DYN>>>(adj);
    k_softmax2<<<Bz * Nn, 256>>>();
    k_av_t   <<<dim3(3, 8, Bz), 256, SMEM_DYN>>>();
    k_out_t  <<<dim3(6, 128),   256, SMEM_DYN>>>(x, bo, out);
}

// round 12
// speedup vs baseline: 1.0144x; 1.0144x over previous
#include <cuda_runtime.h>
#include <cuda_bf16.h>
#include <cstdint>

#define Bz 16
#define Nn 1024
#define Cc 768
#define Dd 384

// All GEMM operands stored as [row][2K] bf16: per 32-k block, 64 elems = [hi32|lo32]
#define LD_X   1536   // 2*768
#define LD_D   768    // 2*384
#define LD_T   2048   // 2*1024

#define TILE_B  16384            // 128 rows x 128B
#define STAGE_B 32768            // A tile + B tile
#define NSTAGE  3
#define SMEM_DYN (NSTAGE*STAGE_B + 128)

// ---------------- static scratch ----------------
__device__ __align__(16) __nv_bfloat16 g_xA2 [(size_t)Bz*Nn*LD_X];
__device__ __align__(16) __nv_bfloat16 g_wB2 [(size_t)3*Dd*LD_X];
__device__              float          g_bias[3*Dd];
__device__ __align__(16) __nv_bfloat16 g_th2 [(size_t)Bz*Nn*LD_D];
__device__ __align__(16) __nv_bfloat16 g_ph2 [(size_t)Bz*Nn*LD_D];
__device__ __align__(16) __nv_bfloat16 g_g2  [(size_t)Bz*Dd*LD_T];
__device__ __align__(16) float         g_attn[(size_t)Bz*Nn*Nn];
__device__ __align__(16) __nv_bfloat16 g_at2 [(size_t)Bz*Nn*LD_T];
__device__ __align__(16) __nv_bfloat16 g_od2 [(size_t)Bz*Nn*LD_D];
__device__ __align__(16) __nv_bfloat16 g_wo2 [(size_t)Cc*LD_D];

// ---------------- helpers ----------------
__device__ __forceinline__ uint32_t smem_u32(const void* p){
    uint32_t a;
    asm("{ .reg .u64 t; cvta.to.shared.u64 t, %1; cvt.u32.u64 %0, t; }" : "=r"(a) : "l"(p));
    return a;
}
__device__ __forceinline__ void cpa16(uint32_t dst, const void* src){
    asm volatile("cp.async.cg.shared.global [%0], [%1], 16;" :: "r"(dst), "l"(src));
}
#define CP_COMMIT() asm volatile("cp.async.commit_group;" ::: "memory")
#define CP_WAIT(N)  asm volatile("cp.async.wait_group %0;" :: "n"(N) : "memory")

__device__ __forceinline__ void ldsm4(uint32_t (&d)[4], uint32_t a){
    asm volatile("ldmatrix.sync.aligned.m8n8.x4.shared.b16 {%0,%1,%2,%3}, [%4];"
        : "=r"(d[0]), "=r"(d[1]), "=r"(d[2]), "=r"(d[3]) : "r"(a));
}
__device__ __forceinline__ void ldsm2(uint32_t (&d)[2], uint32_t a){
    asm volatile("ldmatrix.sync.aligned.m8n8.x2.shared.b16 {%0,%1}, [%2];"
        : "=r"(d[0]), "=r"(d[1]) : "r"(a));
}
__device__ __forceinline__ void mma16816(float (&c)[4], const uint32_t (&a)[4], const uint32_t (&b)[2]){
    asm volatile("mma.sync.aligned.m16n8k16.row.col.f32.bf16.bf16.f32 "
        "{%0,%1,%2,%3}, {%4,%5,%6,%7}, {%8,%9}, {%0,%1,%2,%3};"
        : "+f"(c[0]), "+f"(c[1]), "+f"(c[2]), "+f"(c[3])
        : "r"(a[0]), "r"(a[1]), "r"(a[2]), "r"(a[3]), "r"(b[0]), "r"(b[1]));
}

__device__ __forceinline__ uint32_t bf2u(__nv_bfloat16 a, __nv_bfloat16 b){
    return (uint32_t)__bfloat16_as_ushort(a) | ((uint32_t)__bfloat16_as_ushort(b) << 16);
}
__device__ __forceinline__ void split_bf(float v, __nv_bfloat16& h, __nv_bfloat16& l){
    h = __float2bfloat16(v);
    l = __float2bfloat16(v - __bfloat162float(h));
}
__device__ __forceinline__ void store_hl(__nv_bfloat16* base, int d, float v0, float v1){
    __nv_bfloat16 h0,l0,h1,l1;
    split_bf(v0,h0,l0); split_bf(v1,h1,l1);
    __nv_bfloat16* p = base + ((d >> 5) << 6) + (d & 31);
    *(uint32_t*)(p)      = bf2u(h0,h1);
    *(uint32_t*)(p + 32) = bf2u(l0,l1);
}

// ---------------- 3-term split HMMA GEMM core ----------------
// C ~= Ahi*Bhi + Ahi*Blo + Alo*Bhi per 32-k block from one 32KB stage.
// CTA tile 128x128, 8 warps (2x4), warp tile 64x32.
// R11: fragment loads issued one pass early so LDSM latency hides under MMAs.
__device__ __forceinline__ void gemm3(
    const __nv_bfloat16* __restrict__ A, int ldA,
    const __nv_bfloat16* __restrict__ B, int ldB,
    int nkb, char* sm, float acc[4][4][4])
{
    const int tid  = threadIdx.x;
    const int lane = tid & 31;
    const int w    = tid >> 5;
    const int wr   = w >> 2, wc = w & 3;
    const uint32_t sbase = (smem_u32(sm) + 127u) & ~127u;

    int goA[4], goB[4], smo[4];
#pragma unroll
    for (int i = 0; i < 4; i++){
        int idx = i * 256 + tid;
        int rr = idx >> 3, cc = idx & 7;
        goA[i] = rr * ldA + cc * 8;
        goB[i] = rr * ldB + cc * 8;
        smo[i] = rr * 128 + ((cc * 16) ^ ((rr & 7) << 4));
    }

    const int xorv = (lane & 7) << 4;
    int arow[4], brow[4];
#pragma unroll
    for (int mi = 0; mi < 4; mi++) arow[mi] = (wr * 64 + mi * 16 + (lane & 15)) * 128;
#pragma unroll
    for (int ni = 0; ni < 4; ni++) brow[ni] = (wc * 32 + ni * 8 + (lane & 7)) * 128;
    const int acs = (lane & 16);
    const int bcs = (lane & 8) << 1;

#pragma unroll
    for (int mi = 0; mi < 4; mi++)
#pragma unroll
        for (int ni = 0; ni < 4; ni++)
#pragma unroll
            for (int q = 0; q < 4; q++) acc[mi][ni][q] = 0.f;

    // prologue: issue chunks 0,1
#pragma unroll
    for (int pc = 0; pc < 2; pc++){
        const uint32_t s = sbase + pc * STAGE_B;
        const __nv_bfloat16* Ak = A + pc * 64;
        const __nv_bfloat16* Bk = B + pc * 64;
#pragma unroll
        for (int i = 0; i < 4; i++) cpa16(s + smo[i], Ak + goA[i]);
#pragma unroll
        for (int i = 0; i < 4; i++) cpa16(s + TILE_B + smo[i], Bk + goB[i]);
        CP_COMMIT();
    }

    int stg = 0;
    for (int c = 0; c < nkb; ++c){
        if (c + 1 < nkb) { CP_WAIT(1); } else { CP_WAIT(0); }
        __syncthreads();

        const uint32_t sA = sbase + stg * STAGE_B;
        const uint32_t sB = sA + TILE_B;
#pragma unroll
        for (int ks = 0; ks < 2; ks++){
            const int chA = ((ks << 5) | acs);
            const int chB = ((ks << 5) | bcs);
            uint32_t ahi[4][4], bhi[4][2], blo[4][2];
#pragma unroll
            for (int ni = 0; ni < 4; ni++) ldsm2(bhi[ni], sB + brow[ni] + (chB ^ xorv));
#pragma unroll
            for (int mi = 0; mi < 4; mi++) ldsm4(ahi[mi], sA + arow[mi] + (chA ^ xorv));
            // early-issue B lo fragments: latency hides under pass 1
#pragma unroll
            for (int ni = 0; ni < 4; ni++) ldsm2(blo[ni], sB + brow[ni] + ((chB | 64) ^ xorv));
            // pass 1: hi*hi
#pragma unroll
            for (int ni = 0; ni < 4; ni++)
#pragma unroll
                for (int mi = 0; mi < 4; mi++) mma16816(acc[mi][ni], ahi[mi], bhi[ni]);
            // early-issue A lo fragments: latency hides under pass 2
            uint32_t alo[4][4];
#pragma unroll
            for (int mi = 0; mi < 4; mi++) ldsm4(alo[mi], sA + arow[mi] + ((chA | 64) ^ xorv));
            // pass 2: hi*lo
#pragma unroll
            for (int ni = 0; ni < 4; ni++)
#pragma unroll
                for (int mi = 0; mi < 4; mi++) mma16816(acc[mi][ni], ahi[mi], blo[ni]);
            // pass 3: lo*hi
#pragma unroll
            for (int ni = 0; ni < 4; ni++)
#pragma unroll
                for (int mi = 0; mi < 4; mi++) mma16816(acc[mi][ni], alo[mi], bhi[ni]);
        }

        // issue chunk c+2 into the stage consumed at c-1 (safe: barrier above)
        if (c + 2 < nkb){
            const int ns = (stg + 2 >= NSTAGE) ? stg + 2 - NSTAGE : stg + 2;
            const uint32_t s = sbase + ns * STAGE_B;
            const __nv_bfloat16* Ak = A + (c + 2) * 64;
            const __nv_bfloat16* Bk = B + (c + 2) * 64;
#pragma unroll
            for (int i = 0; i < 4; i++) cpa16(s + smo[i], Ak + goA[i]);
#pragma unroll
            for (int i = 0; i < 4; i++) cpa16(s + TILE_B + smo[i], Bk + goB[i]);
            CP_COMMIT();
        }
        stg = (stg + 1 == NSTAGE) ? 0 : stg + 1;
    }
}

// ---------------- conversion kernels ----------------
__global__ __launch_bounds__(256) void k_cvt_x(const float* __restrict__ x){
    const int idx = blockIdx.x * 256 + threadIdx.x;
    const int m = idx / 192, kq = idx % 192;
    const int k = kq * 4;
    float4 v = *(const float4*)(x + (size_t)m * Cc + k);
    __nv_bfloat16 h0,h1,h2,h3,l0,l1,l2,l3;
    split_bf(v.x,h0,l0); split_bf(v.y,h1,l1); split_bf(v.z,h2,l2); split_bf(v.w,h3,l3);
    __nv_bfloat16* p = g_xA2 + (size_t)m * LD_X + ((k >> 5) << 6) + (k & 31);
    uint2 uh; uh.x = bf2u(h0,h1); uh.y = bf2u(h2,h3);
    uint2 ul; ul.x = bf2u(l0,l1); ul.y = bf2u(l2,l3);
    *(uint2*)(p)      = uh;
    *(uint2*)(p + 32) = ul;
}

__global__ __launch_bounds__(256) void k_cvt_w(
    const float* __restrict__ Wt, const float* __restrict__ bt,
    const float* __restrict__ Wp, const float* __restrict__ bp,
    const float* __restrict__ Wg, const float* __restrict__ bg)
{
    const int idx = blockIdx.x * 256 + threadIdx.x;
    const int n = idx / 192, kq = idx % 192;
    const int which = n / Dd, d = n % Dd;
    const int k = kq * 4;
    const float* W = (which == 0) ? Wt : (which == 1) ? Wp : Wg;
    __nv_bfloat16 h[4], l[4];
#pragma unroll
    for (int t = 0; t < 4; t++)
        split_bf(W[(size_t)(k + t) * Dd + d], h[t], l[t]);
    __nv_bfloat16* p = g_wB2 + (size_t)n * LD_X + ((k >> 5) << 6) + (k & 31);
    uint2 uh; uh.x = bf2u(h[0],h[1]); uh.y = bf2u(h[2],h[3]);
    uint2 ul; ul.x = bf2u(l[0],l[1]); ul.y = bf2u(l[2],l[3]);
    *(uint2*)(p)      = uh;
    *(uint2*)(p + 32) = ul;
    if (kq == 0){
        const float* bb = (which == 0) ? bt : (which == 1) ? bp : bg;
        g_bias[n] = bb[d];
    }
}

__global__ __launch_bounds__(256) void k_cvt_wo(const float* __restrict__ Wo){
    const int idx = blockIdx.x * 256 + threadIdx.x;
    const int n = idx / 96, kq = idx % 96;
    const int k = kq * 4;
    __nv_bfloat16 h[4], l[4];
#pragma unroll
    for (int t = 0; t < 4; t++)
        split_bf(Wo[(size_t)(k + t) * Cc + n], h[t], l[t]);
    __nv_bfloat16* p = g_wo2 + (size_t)n * LD_D + ((k >> 5) << 6) + (k & 31);
    uint2 uh; uh.x = bf2u(h[0],h[1]); uh.y = bf2u(h[2],h[3]);
    uint2 ul; ul.x = bf2u(l[0],l[1]); ul.y = bf2u(l[2],l[3]);
    *(uint2*)(p)      = uh;
    *(uint2*)(p + 32) = ul;
}

// ---------------- GEMM 1: projections ----------------
__global__ __launch_bounds__(256, 2) void k_proj_t(){
    extern __shared__ char sm[];
    const int lane = threadIdx.x & 31, w = threadIdx.x >> 5;
    const int wr = w >> 2, wc = w & 3;
    const int n0 = blockIdx.x * 128, m0 = blockIdx.y * 128;
    float acc[4][4][4];
    gemm3(g_xA2 + (size_t)m0 * LD_X, LD_X,
          g_wB2 + (size_t)n0 * LD_X, LD_X, Cc / 32, sm, acc);

    const int seg = n0 / Dd, d0 = n0 % Dd;
#pragma unroll
    for (int mi = 0; mi < 4; mi++)
#pragma unroll
    for (int ni = 0; ni < 4; ni++)
#pragma unroll
    for (int h = 0; h < 2; h++){
        const int r   = wr * 64 + mi * 16 + (lane >> 2) + h * 8;
        const int col = wc * 32 + ni * 8 + (lane & 3) * 2;
        const int mrow = m0 + r;
        const int ng = n0 + col;
        const float v0 = acc[mi][ni][h * 2]     + g_bias[ng];
        const float v1 = acc[mi][ni][h * 2 + 1] + g_bias[ng + 1];
        const int d = d0 + col;
        if (seg == 0){
            store_hl(g_th2 + (size_t)mrow * LD_D, d, v0, v1);
        } else if (seg == 1){
            store_hl(g_ph2 + (size_t)mrow * LD_D, d, v0, v1);
        } else {
            const int b = mrow >> 10, ml = mrow & 1023;
            const int off = ((ml >> 5) << 6) + (ml & 31);
            __nv_bfloat16 h0, l0, h1, l1;
            split_bf(v0, h0, l0); split_bf(v1, h1, l1);
            __nv_bfloat16* q0 = g_g2 + (size_t)(b * Dd + d)     * LD_T + off;
            __nv_bfloat16* q1 = g_g2 + (size_t)(b * Dd + d + 1) * LD_T + off;
            q0[0] = h0; q0[32] = l0;
            q1[0] = h1; q1[32] = l1;
        }
    }
}

// ---------------- GEMM 2: scores = (theta @ phi^T) * adj ----------------
__global__ __launch_bounds__(256, 2) void k_score_t(const float* __restrict__ adj){
    extern __shared__ char sm[];
    const int lane = threadIdx.x & 31, w = threadIdx.x >> 5;
    const int wr = w >> 2, wc = w & 3;
    const int b = blockIdx.z, j0 = blockIdx.x * 128, i0 = blockIdx.y * 128;
    float acc[4][4][4];
    gemm3(g_th2 + (size_t)(b * Nn + i0) * LD_D, LD_D,
          g_ph2 + (size_t)(b * Nn + j0) * LD_D, LD_D, Dd / 32, sm, acc);

#pragma unroll
    for (int mi = 0; mi < 4; mi++)
#pragma unroll
    for (int ni = 0; ni < 4; ni++)
#pragma unroll
    for (int h = 0; h < 2; h++){
        const int i = i0 + wr * 64 + mi * 16 + (lane >> 2) + h * 8;
        const int j = j0 + wc * 32 + ni * 8 + (lane & 3) * 2;
        const size_t idx = ((size_t)b * Nn + i) * Nn + j;
        const float2 a2 = *(const float2*)(adj + idx);
        float2 o;
        o.x = acc[mi][ni][h * 2]     * a2.x;
        o.y = acc[mi][ni][h * 2 + 1] * a2.y;
        *(float2*)(g_attn + idx) = o;
    }
}

// ---------------- softmax + hi|lo split ----------------
__global__ __launch_bounds__(256) void k_softmax2(){
    const size_t row = blockIdx.x;
    const float4 v = ((const float4*)(g_attn + row * Nn))[threadIdx.x];

    float m = fmaxf(fmaxf(v.x, v.y), fmaxf(v.z, v.w));
#pragma unroll
    for (int o = 16; o; o >>= 1) m = fmaxf(m, __shfl_xor_sync(0xffffffffu, m, o));
    __shared__ float red[8];
    const int warp = threadIdx.x >> 5;
    if ((threadIdx.x & 31) == 0) red[warp] = m;
    __syncthreads();
    float bm = red[0];
#pragma unroll
    for (int i = 1; i < 8; i++) bm = fmaxf(bm, red[i]);
    __syncthreads();

    float4 e;
    e.x = __expf(v.x - bm); e.y = __expf(v.y - bm);
    e.z = __expf(v.z - bm); e.w = __expf(v.w - bm);
    float s = e.x + e.y + e.z + e.w;
#pragma unroll
    for (int o = 16; o; o >>= 1) s += __shfl_xor_sync(0xffffffffu, s, o);
    if ((threadIdx.x & 31) == 0) red[warp] = s;
    __syncthreads();
    float tot = red[0];
#pragma unroll
    for (int i = 1; i < 8; i++) tot += red[i];
    const float inv = 1.0f / tot;
    e.x *= inv; e.y *= inv; e.z *= inv; e.w *= inv;

    const int t = threadIdx.x * 4;
    __nv_bfloat16 h0,h1,h2,h3,l0,l1,l2,l3;
    split_bf(e.x,h0,l0); split_bf(e.y,h1,l1); split_bf(e.z,h2,l2); split_bf(e.w,h3,l3);
    __nv_bfloat16* p = g_at2 + row * LD_T + ((t >> 5) << 6) + (t & 31);
    uint2 uh; uh.x = bf2u(h0,h1); uh.y = bf2u(h2,h3);
    uint2 ul; ul.x = bf2u(l0,l1); ul.y = bf2u(l2,l3);
    *(uint2*)(p)      = uh;
    *(uint2*)(p + 32) = ul;
}

// ---------------- GEMM 3: attn @ g ----------------
__global__ __launch_bounds__(256, 2) void k_av_t(){
    extern __shared__ char sm[];
    const int lane = threadIdx.x & 31, w = threadIdx.x >> 5;
    const int wr = w >> 2, wc = w & 3;
    const int b = blockIdx.z, n0 = blockIdx.x * 128, i0 = blockIdx.y * 128;
    float acc[4][4][4];
    gemm3(g_at2 + (size_t)(b * Nn + i0) * LD_T, LD_T,
          g_g2  + (size_t)(b * Dd + n0) * LD_T, LD_T, Nn / 32, sm, acc);

#pragma unroll
    for (int mi = 0; mi < 4; mi++)
#pragma unroll
    for (int ni = 0; ni < 4; ni++)
#pragma unroll
    for (int h = 0; h < 2; h++){
        const int r   = wr * 64 + mi * 16 + (lane >> 2) + h * 8;
        const int col = wc * 32 + ni * 8 + (lane & 3) * 2;
        const int mrow = b * Nn + i0 + r;
        store_hl(g_od2 + (size_t)mrow * LD_D, n0 + col,
                 acc[mi][ni][h * 2], acc[mi][ni][h * 2 + 1]);
    }
}

// ---------------- GEMM 4: output + bias + residual ----------------
__global__ __launch_bounds__(256, 2) void k_out_t(
    const float* __restrict__ x, const float* __restrict__ bo, float* __restrict__ out)
{
    extern __shared__ char sm[];
    const int lane = threadIdx.x & 31, w = threadIdx.x >> 5;
    const int wr = w >> 2, wc = w & 3;
    const int n0 = blockIdx.x * 128, m0 = blockIdx.y * 128;
    float acc[4][4][4];
    gemm3(g_od2 + (size_t)m0 * LD_D, LD_D,
          g_wo2 + (size_t)n0 * LD_D, LD_D, Dd / 32, sm, acc);

#pragma unroll
    for (int mi = 0; mi < 4; mi++)
#pragma unroll
    for (int ni = 0; ni < 4; ni++)
#pragma unroll
    for (int h = 0; h < 2; h++){
        const int row = m0 + wr * 64 + mi * 16 + (lane >> 2) + h * 8;
        const int cg  = n0 + wc * 32 + ni * 8 + (lane & 3) * 2;
        const size_t idx = (size_t)row * Cc + cg;
        const float2 xv = *(const float2*)(x + idx);
        const float2 bv = *(const float2*)(bo + cg);
        float2 o;
        o.x = acc[mi][ni][h * 2]     + bv.x + xv.x;
        o.y = acc[mi][ni][h * 2 + 1] + bv.y + xv.y;
        *(float2*)(out + idx) = o;
    }
}

// ---------------------------------------------------------------------------
extern "C" void kernel_launch(void* const* d_in, const int* in_sizes, int n_in,
                              void* d_out, int out_size)
{
    const float* x  = (const float*)d_in[0];
    const float* adj = (const float*)d_in[1];
    const float* Wt = (const float*)d_in[2];
    const float* bt = (const float*)d_in[3];
    const float* Wp = (const float*)d_in[4];
    const float* bp = (const float*)d_in[5];
    const float* Wg = (const float*)d_in[6];
    const float* bg = (const float*)d_in[7];
    const float* Wo = (const float*)d_in[8];
    const float* bo = (const float*)d_in[9];
    float* out = (float*)d_out;

    static bool attr_done = false;
    if (!attr_done){
        cudaFuncSetAttribute(k_proj_t,  cudaFuncAttributeMaxDynamicSharedMemorySize, SMEM_DYN);
        cudaFuncSetAttribute(k_score_t, cudaFuncAttributeMaxDynamicSharedMemorySize, SMEM_DYN);
        cudaFuncSetAttribute(k_av_t,    cudaFuncAttributeMaxDynamicSharedMemorySize, SMEM_DYN);
        cudaFuncSetAttribute(k_out_t,   cudaFuncAttributeMaxDynamicSharedMemorySize, SMEM_DYN);
        attr_done = true;
    }

    k_cvt_x <<<(Bz * Nn * 192) / 256, 256>>>(x);
    k_cvt_w <<<(3 * Dd * 192) / 256, 256>>>(Wt, bt, Wp, bp, Wg, bg);
    k_cvt_wo<<<(Cc * 96) / 256, 256>>>(Wo);

    k_proj_t <<<dim3(9, 128),   256, SMEM_DYN>>>();
    k_score_t<<<dim3(8, 8, Bz), 256, SMEM_DYN>>>(adj);
    k_softmax2<<<Bz * Nn, 256>>>();
    k_av_t   <<<dim3(3, 8, Bz), 256, SMEM_DYN>>>();
    k_out_t  <<<dim3(6, 128),   256, SMEM_DYN>>>(x, bo, out);
}

// round 13
// speedup vs baseline: 1.3618x; 1.3424x over previous
#include <cuda_runtime.h>
#include <cuda_fp16.h>
#include <cstdint>

#define Bz 16
#define Nn 1024
#define Cc 768
#define Dd 384

// All GEMM operands stored as [row][2K] fp16: per 32-k block, 64 elems = [hi32|lo32]
#define LD_X   1536   // 2*768
#define LD_D   768    // 2*384
#define LD_T   2048   // 2*1024

#define TILE_B  16384            // 128 rows x 128B
#define STAGE_B 32768            // A tile + B tile
#define NSTAGE  3
#define SMEM_DYN (NSTAGE*STAGE_B + 128)

// ---------------- static scratch ----------------
__device__ __align__(16) __half g_xA2 [(size_t)Bz*Nn*LD_X];
__device__ __align__(16) __half g_wB2 [(size_t)3*Dd*LD_X];
__device__              float   g_bias[3*Dd];
__device__ __align__(16) __half g_th2 [(size_t)Bz*Nn*LD_D];
__device__ __align__(16) __half g_ph2 [(size_t)Bz*Nn*LD_D];
__device__ __align__(16) __half g_g2  [(size_t)Bz*Dd*LD_T];
__device__ __align__(16) float  g_attn[(size_t)Bz*Nn*Nn];
__device__ __align__(16) __half g_at2 [(size_t)Bz*Nn*LD_T];
__device__ __align__(16) __half g_od2 [(size_t)Bz*Nn*LD_D];
__device__ __align__(16) __half g_wo2 [(size_t)Cc*LD_D];

// ---------------- helpers ----------------
__device__ __forceinline__ uint32_t smem_u32(const void* p){
    uint32_t a;
    asm("{ .reg .u64 t; cvta.to.shared.u64 t, %1; cvt.u32.u64 %0, t; }" : "=r"(a) : "l"(p));
    return a;
}
__device__ __forceinline__ void cpa16(uint32_t dst, const void* src){
    asm volatile("cp.async.cg.shared.global [%0], [%1], 16;" :: "r"(dst), "l"(src));
}
#define CP_COMMIT() asm volatile("cp.async.commit_group;" ::: "memory")
#define CP_WAIT(N)  asm volatile("cp.async.wait_group %0;" :: "n"(N) : "memory")

__device__ __forceinline__ void ldsm4(uint32_t (&d)[4], uint32_t a){
    asm volatile("ldmatrix.sync.aligned.m8n8.x4.shared.b16 {%0,%1,%2,%3}, [%4];"
        : "=r"(d[0]), "=r"(d[1]), "=r"(d[2]), "=r"(d[3]) : "r"(a));
}
__device__ __forceinline__ void ldsm2(uint32_t (&d)[2], uint32_t a){
    asm volatile("ldmatrix.sync.aligned.m8n8.x2.shared.b16 {%0,%1}, [%2];"
        : "=r"(d[0]), "=r"(d[1]) : "r"(a));
}
__device__ __forceinline__ void mma16816(float (&c)[4], const uint32_t (&a)[4], const uint32_t (&b)[2]){
    asm volatile("mma.sync.aligned.m16n8k16.row.col.f32.f16.f16.f32 "
        "{%0,%1,%2,%3}, {%4,%5,%6,%7}, {%8,%9}, {%0,%1,%2,%3};"
        : "+f"(c[0]), "+f"(c[1]), "+f"(c[2]), "+f"(c[3])
        : "r"(a[0]), "r"(a[1]), "r"(a[2]), "r"(a[3]), "r"(b[0]), "r"(b[1]));
}

__device__ __forceinline__ uint32_t h2u2(__half a, __half b){
    return (uint32_t)__half_as_ushort(a) | ((uint32_t)__half_as_ushort(b) << 16);
}
__device__ __forceinline__ void split_h(float v, __half& h, __half& l){
    h = __float2half_rn(v);
    l = __float2half_rn(v - __half2float(h));
}
__device__ __forceinline__ void store_hl(__half* base, int d, float v0, float v1){
    __half h0,l0,h1,l1;
    split_h(v0,h0,l0); split_h(v1,h1,l1);
    __half* p = base + ((d >> 5) << 6) + (d & 31);
    *(uint32_t*)(p)      = h2u2(h0,h1);
    *(uint32_t*)(p + 32) = h2u2(l0,l1);
}

// ---------------- 2-term split HMMA GEMM core (fp16) ----------------
// C ~= (Ahi+Alo)*Bhi  =  Ahi*Bhi + Alo*Bhi per 32-k block from one 32KB stage.
// Residual error ~ A*Blo ~ 2^-11 relative (threshold 1e-3).
// CTA tile 128x128, 8 warps (2x4), warp tile 64x32.
__device__ __forceinline__ void gemm2(
    const __half* __restrict__ A, int ldA,
    const __half* __restrict__ B, int ldB,
    int nkb, char* sm, float acc[4][4][4])
{
    const int tid  = threadIdx.x;
    const int lane = tid & 31;
    const int w    = tid >> 5;
    const int wr   = w >> 2, wc = w & 3;
    const uint32_t sbase = (smem_u32(sm) + 127u) & ~127u;

    int goA[4], goB[4], smo[4];
#pragma unroll
    for (int i = 0; i < 4; i++){
        int idx = i * 256 + tid;
        int rr = idx >> 3, cc = idx & 7;
        goA[i] = rr * ldA + cc * 8;
        goB[i] = rr * ldB + cc * 8;
        smo[i] = rr * 128 + ((cc * 16) ^ ((rr & 7) << 4));
    }

    const int xorv = (lane & 7) << 4;
    int arow[4], brow[4];
#pragma unroll
    for (int mi = 0; mi < 4; mi++) arow[mi] = (wr * 64 + mi * 16 + (lane & 15)) * 128;
#pragma unroll
    for (int ni = 0; ni < 4; ni++) brow[ni] = (wc * 32 + ni * 8 + (lane & 7)) * 128;
    const int acs = (lane & 16);
    const int bcs = (lane & 8) << 1;

#pragma unroll
    for (int mi = 0; mi < 4; mi++)
#pragma unroll
        for (int ni = 0; ni < 4; ni++)
#pragma unroll
            for (int q = 0; q < 4; q++) acc[mi][ni][q] = 0.f;

    // prologue: issue chunks 0,1
#pragma unroll
    for (int pc = 0; pc < 2; pc++){
        const uint32_t s = sbase + pc * STAGE_B;
        const __half* Ak = A + pc * 64;
        const __half* Bk = B + pc * 64;
#pragma unroll
        for (int i = 0; i < 4; i++) cpa16(s + smo[i], Ak + goA[i]);
#pragma unroll
        for (int i = 0; i < 4; i++) cpa16(s + TILE_B + smo[i], Bk + goB[i]);
        CP_COMMIT();
    }

    int stg = 0;
    for (int c = 0; c < nkb; ++c){
        if (c + 1 < nkb) { CP_WAIT(1); } else { CP_WAIT(0); }
        __syncthreads();

        const uint32_t sA = sbase + stg * STAGE_B;
        const uint32_t sB = sA + TILE_B;
#pragma unroll
        for (int ks = 0; ks < 2; ks++){
            const int chA = ((ks << 5) | acs);
            const int chB = ((ks << 5) | bcs);
            uint32_t ahi[4][4], bhi[4][2];
#pragma unroll
            for (int ni = 0; ni < 4; ni++) ldsm2(bhi[ni], sB + brow[ni] + (chB ^ xorv));
#pragma unroll
            for (int mi = 0; mi < 4; mi++) ldsm4(ahi[mi], sA + arow[mi] + (chA ^ xorv));
            // pass 1: Ahi * Bhi
#pragma unroll
            for (int ni = 0; ni < 4; ni++)
#pragma unroll
                for (int mi = 0; mi < 4; mi++) mma16816(acc[mi][ni], ahi[mi], bhi[ni]);
            // pass 2: Alo * Bhi (reuse ahi regs)
#pragma unroll
            for (int mi = 0; mi < 4; mi++) ldsm4(ahi[mi], sA + arow[mi] + ((chA | 64) ^ xorv));
#pragma unroll
            for (int ni = 0; ni < 4; ni++)
#pragma unroll
                for (int mi = 0; mi < 4; mi++) mma16816(acc[mi][ni], ahi[mi], bhi[ni]);
        }

        // issue chunk c+2 into the stage consumed at c-1 (safe: barrier above)
        if (c + 2 < nkb){
            const int ns = (stg + 2 >= NSTAGE) ? stg + 2 - NSTAGE : stg + 2;
            const uint32_t s = sbase + ns * STAGE_B;
            const __half* Ak = A + (c + 2) * 64;
            const __half* Bk = B + (c + 2) * 64;
#pragma unroll
            for (int i = 0; i < 4; i++) cpa16(s + smo[i], Ak + goA[i]);
#pragma unroll
            for (int i = 0; i < 4; i++) cpa16(s + TILE_B + smo[i], Bk + goB[i]);
            CP_COMMIT();
        }
        stg = (stg + 1 == NSTAGE) ? 0 : stg + 1;
    }
}

// ---------------- conversion kernels ----------------
__global__ __launch_bounds__(256) void k_cvt_x(const float* __restrict__ x){
    const int idx = blockIdx.x * 256 + threadIdx.x;
    const int m = idx / 192, kq = idx % 192;
    const int k = kq * 4;
    float4 v = *(const float4*)(x + (size_t)m * Cc + k);
    __half h0,h1,h2,h3,l0,l1,l2,l3;
    split_h(v.x,h0,l0); split_h(v.y,h1,l1); split_h(v.z,h2,l2); split_h(v.w,h3,l3);
    __half* p = g_xA2 + (size_t)m * LD_X + ((k >> 5) << 6) + (k & 31);
    uint2 uh; uh.x = h2u2(h0,h1); uh.y = h2u2(h2,h3);
    uint2 ul; ul.x = h2u2(l0,l1); ul.y = h2u2(l2,l3);
    *(uint2*)(p)      = uh;
    *(uint2*)(p + 32) = ul;
}

__global__ __launch_bounds__(256) void k_cvt_w(
    const float* __restrict__ Wt, const float* __restrict__ bt,
    const float* __restrict__ Wp, const float* __restrict__ bp,
    const float* __restrict__ Wg, const float* __restrict__ bg)
{
    const int idx = blockIdx.x * 256 + threadIdx.x;
    const int n = idx / 192, kq = idx % 192;
    const int which = n / Dd, d = n % Dd;
    const int k = kq * 4;
    const float* W = (which == 0) ? Wt : (which == 1) ? Wp : Wg;
    __half h[4], l[4];
#pragma unroll
    for (int t = 0; t < 4; t++)
        split_h(W[(size_t)(k + t) * Dd + d], h[t], l[t]);
    __half* p = g_wB2 + (size_t)n * LD_X + ((k >> 5) << 6) + (k & 31);
    uint2 uh; uh.x = h2u2(h[0],h[1]); uh.y = h2u2(h[2],h[3]);
    uint2 ul; ul.x = h2u2(l[0],l[1]); ul.y = h2u2(l[2],l[3]);
    *(uint2*)(p)      = uh;
    *(uint2*)(p + 32) = ul;
    if (kq == 0){
        const float* bb = (which == 0) ? bt : (which == 1) ? bp : bg;
        g_bias[n] = bb[d];
    }
}

__global__ __launch_bounds__(256) void k_cvt_wo(const float* __restrict__ Wo){
    const int idx = blockIdx.x * 256 + threadIdx.x;
    const int n = idx / 96, kq = idx % 96;
    const int k = kq * 4;
    __half h[4], l[4];
#pragma unroll
    for (int t = 0; t < 4; t++)
        split_h(Wo[(size_t)(k + t) * Cc + n], h[t], l[t]);
    __half* p = g_wo2 + (size_t)n * LD_D + ((k >> 5) << 6) + (k & 31);
    uint2 uh; uh.x = h2u2(h[0],h[1]); uh.y = h2u2(h[2],h[3]);
    uint2 ul; ul.x = h2u2(l[0],l[1]); ul.y = h2u2(l[2],l[3]);
    *(uint2*)(p)      = uh;
    *(uint2*)(p + 32) = ul;
}

// ---------------- GEMM 1: projections ----------------
__global__ __launch_bounds__(256, 2) void k_proj_t(){
    extern __shared__ char sm[];
    const int lane = threadIdx.x & 31, w = threadIdx.x >> 5;
    const int wr = w >> 2, wc = w & 3;
    const int n0 = blockIdx.x * 128, m0 = blockIdx.y * 128;
    float acc[4][4][4];
    gemm2(g_xA2 + (size_t)m0 * LD_X, LD_X,
          g_wB2 + (size_t)n0 * LD_X, LD_X, Cc / 32, sm, acc);

    const int seg = n0 / Dd, d0 = n0 % Dd;
#pragma unroll
    for (int mi = 0; mi < 4; mi++)
#pragma unroll
    for (int ni = 0; ni < 4; ni++)
#pragma unroll
    for (int h = 0; h < 2; h++){
        const int r   = wr * 64 + mi * 16 + (lane >> 2) + h * 8;
        const int col = wc * 32 + ni * 8 + (lane & 3) * 2;
        const int mrow = m0 + r;
        const int ng = n0 + col;
        const float v0 = acc[mi][ni][h * 2]     + g_bias[ng];
        const float v1 = acc[mi][ni][h * 2 + 1] + g_bias[ng + 1];
        const int d = d0 + col;
        if (seg == 0){
            store_hl(g_th2 + (size_t)mrow * LD_D, d, v0, v1);
        } else if (seg == 1){
            store_hl(g_ph2 + (size_t)mrow * LD_D, d, v0, v1);
        } else {
            const int b = mrow >> 10, ml = mrow & 1023;
            const int off = ((ml >> 5) << 6) + (ml & 31);
            __half h0, l0, h1, l1;
            split_h(v0, h0, l0); split_h(v1, h1, l1);
            __half* q0 = g_g2 + (size_t)(b * Dd + d)     * LD_T + off;
            __half* q1 = g_g2 + (size_t)(b * Dd + d + 1) * LD_T + off;
            q0[0] = h0; q0[32] = l0;
            q1[0] = h1; q1[32] = l1;
        }
    }
}

// ---------------- GEMM 2: scores = (theta @ phi^T) * adj ----------------
__global__ __launch_bounds__(256, 2) void k_score_t(const float* __restrict__ adj){
    extern __shared__ char sm[];
    const int lane = threadIdx.x & 31, w = threadIdx.x >> 5;
    const int wr = w >> 2, wc = w & 3;
    const int b = blockIdx.z, j0 = blockIdx.x * 128, i0 = blockIdx.y * 128;
    float acc[4][4][4];
    gemm2(g_th2 + (size_t)(b * Nn + i0) * LD_D, LD_D,
          g_ph2 + (size_t)(b * Nn + j0) * LD_D, LD_D, Dd / 32, sm, acc);

#pragma unroll
    for (int mi = 0; mi < 4; mi++)
#pragma unroll
    for (int ni = 0; ni < 4; ni++)
#pragma unroll
    for (int h = 0; h < 2; h++){
        const int i = i0 + wr * 64 + mi * 16 + (lane >> 2) + h * 8;
        const int j = j0 + wc * 32 + ni * 8 + (lane & 3) * 2;
        const size_t idx = ((size_t)b * Nn + i) * Nn + j;
        const float2 a2 = *(const float2*)(adj + idx);
        float2 o;
        o.x = acc[mi][ni][h * 2]     * a2.x;
        o.y = acc[mi][ni][h * 2 + 1] * a2.y;
        *(float2*)(g_attn + idx) = o;
    }
}

// ---------------- softmax + hi|lo split ----------------
__global__ __launch_bounds__(256) void k_softmax2(){
    const size_t row = blockIdx.x;
    const float4 v = ((const float4*)(g_attn + row * Nn))[threadIdx.x];

    float m = fmaxf(fmaxf(v.x, v.y), fmaxf(v.z, v.w));
#pragma unroll
    for (int o = 16; o; o >>= 1) m = fmaxf(m, __shfl_xor_sync(0xffffffffu, m, o));
    __shared__ float red[8];
    const int warp = threadIdx.x >> 5;
    if ((threadIdx.x & 31) == 0) red[warp] = m;
    __syncthreads();
    float bm = red[0];
#pragma unroll
    for (int i = 1; i < 8; i++) bm = fmaxf(bm, red[i]);
    __syncthreads();

    float4 e;
    e.x = __expf(v.x - bm); e.y = __expf(v.y - bm);
    e.z = __expf(v.z - bm); e.w = __expf(v.w - bm);
    float s = e.x + e.y + e.z + e.w;
#pragma unroll
    for (int o = 16; o; o >>= 1) s += __shfl_xor_sync(0xffffffffu, s, o);
    if ((threadIdx.x & 31) == 0) red[warp] = s;
    __syncthreads();
    float tot = red[0];
#pragma unroll
    for (int i = 1; i < 8; i++) tot += red[i];
    const float inv = 1.0f / tot;
    e.x *= inv; e.y *= inv; e.z *= inv; e.w *= inv;

    const int t = threadIdx.x * 4;
    __half h0,h1,h2,h3,l0,l1,l2,l3;
    split_h(e.x,h0,l0); split_h(e.y,h1,l1); split_h(e.z,h2,l2); split_h(e.w,h3,l3);
    __half* p = g_at2 + row * LD_T + ((t >> 5) << 6) + (t & 31);
    uint2 uh; uh.x = h2u2(h0,h1); uh.y = h2u2(h2,h3);
    uint2 ul; ul.x = h2u2(l0,l1); ul.y = h2u2(l2,l3);
    *(uint2*)(p)      = uh;
    *(uint2*)(p + 32) = ul;
}

// ---------------- GEMM 3: attn @ g ----------------
__global__ __launch_bounds__(256, 2) void k_av_t(){
    extern __shared__ char sm[];
    const int lane = threadIdx.x & 31, w = threadIdx.x >> 5;
    const int wr = w >> 2, wc = w & 3;
    const int b = blockIdx.z, n0 = blockIdx.x * 128, i0 = blockIdx.y * 128;
    float acc[4][4][4];
    gemm2(g_at2 + (size_t)(b * Nn + i0) * LD_T, LD_T,
          g_g2  + (size_t)(b * Dd + n0) * LD_T, LD_T, Nn / 32, sm, acc);

#pragma unroll
    for (int mi = 0; mi < 4; mi++)
#pragma unroll
    for (int ni = 0; ni < 4; ni++)
#pragma unroll
    for (int h = 0; h < 2; h++){
        const int r   = wr * 64 + mi * 16 + (lane >> 2) + h * 8;
        const int col = wc * 32 + ni * 8 + (lane & 3) * 2;
        const int mrow = b * Nn + i0 + r;
        store_hl(g_od2 + (size_t)mrow * LD_D, n0 + col,
                 acc[mi][ni][h * 2], acc[mi][ni][h * 2 + 1]);
    }
}

// ---------------- GEMM 4: output + bias + residual ----------------
__global__ __launch_bounds__(256, 2) void k_out_t(
    const float* __restrict__ x, const float* __restrict__ bo, float* __restrict__ out)
{
    extern __shared__ char sm[];
    const int lane = threadIdx.x & 31, w = threadIdx.x >> 5;
    const int wr = w >> 2, wc = w & 3;
    const int n0 = blockIdx.x * 128, m0 = blockIdx.y * 128;
    float acc[4][4][4];
    gemm2(g_od2 + (size_t)m0 * LD_D, LD_D,
          g_wo2 + (size_t)n0 * LD_D, LD_D, Dd / 32, sm, acc);

#pragma unroll
    for (int mi = 0; mi < 4; mi++)
#pragma unroll
    for (int ni = 0; ni < 4; ni++)
#pragma unroll
    for (int h = 0; h < 2; h++){
        const int row = m0 + wr * 64 + mi * 16 + (lane >> 2) + h * 8;
        const int cg  = n0 + wc * 32 + ni * 8 + (lane & 3) * 2;
        const size_t idx = (size_t)row * Cc + cg;
        const float2 xv = *(const float2*)(x + idx);
        const float2 bv = *(const float2*)(bo + cg);
        float2 o;
        o.x = acc[mi][ni][h * 2]     + bv.x + xv.x;
        o.y = acc[mi][ni][h * 2 + 1] + bv.y + xv.y;
        *(float2*)(out + idx) = o;
    }
}

// ---------------------------------------------------------------------------
extern "C" void kernel_launch(void* const* d_in, const int* in_sizes, int n_in,
                              void* d_out, int out_size)
{
    const float* x  = (const float*)d_in[0];
    const float* adj = (const float*)d_in[1];
    const float* Wt = (const float*)d_in[2];
    const float* bt = (const float*)d_in[3];
    const float* Wp = (const float*)d_in[4];
    const float* bp = (const float*)d_in[5];
    const float* Wg = (const float*)d_in[6];
    const float* bg = (const float*)d_in[7];
    const float* Wo = (const float*)d_in[8];
    const float* bo = (const float*)d_in[9];
    float* out = (float*)d_out;

    static bool attr_done = false;
    if (!attr_done){
        cudaFuncSetAttribute(k_proj_t,  cudaFuncAttributeMaxDynamicSharedMemorySize, SMEM_DYN);
        cudaFuncSetAttribute(k_score_t, cudaFuncAttributeMaxDynamicSharedMemorySize, SMEM_DYN);
        cudaFuncSetAttribute(k_av_t,    cudaFuncAttributeMaxDynamicSharedMemorySize, SMEM_DYN);
        cudaFuncSetAttribute(k_out_t,   cudaFuncAttributeMaxDynamicSharedMemorySize, SMEM_DYN);
        attr_done = true;
    }

    k_cvt_x <<<(Bz * Nn * 192) / 256, 256>>>(x);
    k_cvt_w <<<(3 * Dd * 192) / 256, 256>>>(Wt, bt, Wp, bp, Wg, bg);
    k_cvt_wo<<<(Cc * 96) / 256, 256>>>(Wo);

    k_proj_t <<<dim3(9, 128),   256, SMEM_DYN>>>();
    k_score_t<<<dim3(8, 8, Bz), 256, SMEM_DYN>>>(adj);
    k_softmax2<<<Bz * Nn, 256>>>();
    k_av_t   <<<dim3(3, 8, Bz), 256, SMEM_DYN>>>();
    k_out_t  <<<dim3(6, 128),   256, SMEM_DYN>>>(x, bo, out);
}

// round 14
// speedup vs baseline: 2.1813x; 1.6018x over previous
#include <cuda_runtime.h>
#include <cuda_fp16.h>
#include <cstdint>

#define Bz 16
#define Nn 1024
#define Cc 768
#define Dd 384

#define TILE_B  16384            // 128 rows x 128B (64 fp16 k-elems per row)
#define STAGE_B 32768            // A tile + B tile
#define NSTAGE  3
#define SMEM_DYN (NSTAGE*STAGE_B + 128)

// ---------------- static scratch (plain fp16, LD = K) ----------------
__device__ __align__(16) __half g_xh [(size_t)Bz*Nn*Cc];     // A in proj
__device__ __align__(16) __half g_wh [(size_t)3*Dd*Cc];      // B in proj (row n, col k)
__device__              float   g_bias[3*Dd];
__device__ __align__(16) __half g_th [(size_t)Bz*Nn*Dd];     // A in score
__device__ __align__(16) __half g_ph [(size_t)Bz*Nn*Dd];     // B in score
__device__ __align__(16) __half g_gh [(size_t)Bz*Dd*Nn];     // B in av (row d, col token)
__device__ __align__(16) float  g_attn[(size_t)Bz*Nn*Nn];
__device__ __align__(16) __half g_ath[(size_t)Bz*Nn*Nn];     // A in av (softmax rows)
__device__ __align__(16) __half g_odh[(size_t)Bz*Nn*Dd];     // A in out
__device__ __align__(16) __half g_woh[(size_t)Cc*Dd];        // B in out

// ---------------- helpers ----------------
__device__ __forceinline__ uint32_t smem_u32(const void* p){
    uint32_t a;
    asm("{ .reg .u64 t; cvta.to.shared.u64 t, %1; cvt.u32.u64 %0, t; }" : "=r"(a) : "l"(p));
    return a;
}
__device__ __forceinline__ void cpa16(uint32_t dst, const void* src){
    asm volatile("cp.async.cg.shared.global [%0], [%1], 16;" :: "r"(dst), "l"(src));
}
#define CP_COMMIT() asm volatile("cp.async.commit_group;" ::: "memory")
#define CP_WAIT(N)  asm volatile("cp.async.wait_group %0;" :: "n"(N) : "memory")

__device__ __forceinline__ void ldsm4(uint32_t (&d)[4], uint32_t a){
    asm volatile("ldmatrix.sync.aligned.m8n8.x4.shared.b16 {%0,%1,%2,%3}, [%4];"
        : "=r"(d[0]), "=r"(d[1]), "=r"(d[2]), "=r"(d[3]) : "r"(a));
}
__device__ __forceinline__ void ldsm2(uint32_t (&d)[2], uint32_t a){
    asm volatile("ldmatrix.sync.aligned.m8n8.x2.shared.b16 {%0,%1}, [%2];"
        : "=r"(d[0]), "=r"(d[1]) : "r"(a));
}
__device__ __forceinline__ void mma16816(float (&c)[4], const uint32_t (&a)[4], const uint32_t (&b)[2]){
    asm volatile("mma.sync.aligned.m16n8k16.row.col.f32.f16.f16.f32 "
        "{%0,%1,%2,%3}, {%4,%5,%6,%7}, {%8,%9}, {%0,%1,%2,%3};"
        : "+f"(c[0]), "+f"(c[1]), "+f"(c[2]), "+f"(c[3])
        : "r"(a[0]), "r"(a[1]), "r"(a[2]), "r"(a[3]), "r"(b[0]), "r"(b[1]));
}

__device__ __forceinline__ uint32_t h2u2(__half a, __half b){
    return (uint32_t)__half_as_ushort(a) | ((uint32_t)__half_as_ushort(b) << 16);
}

// ---------------- pure fp16 HMMA GEMM core ----------------
// Chunk = 64 k (128B rows). CTA tile 128x128, 8 warps (2x4), warp tile 64x32.
// Same 3-stage pipeline as the proven R12 core; single pass per k16.
__device__ __forceinline__ void gemm1(
    const __half* __restrict__ A, int ldA,
    const __half* __restrict__ B, int ldB,
    int nkb, char* sm, float acc[4][4][4])
{
    const int tid  = threadIdx.x;
    const int lane = tid & 31;
    const int w    = tid >> 5;
    const int wr   = w >> 2, wc = w & 3;
    const uint32_t sbase = (smem_u32(sm) + 127u) & ~127u;

    int goA[4], goB[4], smo[4];
#pragma unroll
    for (int i = 0; i < 4; i++){
        int idx = i * 256 + tid;
        int rr = idx >> 3, cc = idx & 7;
        goA[i] = rr * ldA + cc * 8;
        goB[i] = rr * ldB + cc * 8;
        smo[i] = rr * 128 + ((cc * 16) ^ ((rr & 7) << 4));
    }

    const int xorv = (lane & 7) << 4;
    int arow[4], brow[4];
#pragma unroll
    for (int mi = 0; mi < 4; mi++) arow[mi] = (wr * 64 + mi * 16 + (lane & 15)) * 128;
#pragma unroll
    for (int ni = 0; ni < 4; ni++) brow[ni] = (wc * 32 + ni * 8 + (lane & 7)) * 128;
    const int acs = (lane & 16);
    const int bcs = (lane & 8) << 1;

#pragma unroll
    for (int mi = 0; mi < 4; mi++)
#pragma unroll
        for (int ni = 0; ni < 4; ni++)
#pragma unroll
            for (int q = 0; q < 4; q++) acc[mi][ni][q] = 0.f;

    // prologue: issue chunks 0,1
#pragma unroll
    for (int pc = 0; pc < 2; pc++){
        const uint32_t s = sbase + pc * STAGE_B;
        const __half* Ak = A + pc * 64;
        const __half* Bk = B + pc * 64;
#pragma unroll
        for (int i = 0; i < 4; i++) cpa16(s + smo[i], Ak + goA[i]);
#pragma unroll
        for (int i = 0; i < 4; i++) cpa16(s + TILE_B + smo[i], Bk + goB[i]);
        CP_COMMIT();
    }

    int stg = 0;
    for (int c = 0; c < nkb; ++c){
        if (c + 1 < nkb) { CP_WAIT(1); } else { CP_WAIT(0); }
        __syncthreads();

        const uint32_t sA = sbase + stg * STAGE_B;
        const uint32_t sB = sA + TILE_B;
#pragma unroll
        for (int ks = 0; ks < 4; ks++){
            const int chA = ((ks << 5) | acs);
            const int chB = ((ks << 5) | bcs);
            uint32_t ahi[4][4], bhi[4][2];
#pragma unroll
            for (int ni = 0; ni < 4; ni++) ldsm2(bhi[ni], sB + brow[ni] + (chB ^ xorv));
#pragma unroll
            for (int mi = 0; mi < 4; mi++) ldsm4(ahi[mi], sA + arow[mi] + (chA ^ xorv));
#pragma unroll
            for (int ni = 0; ni < 4; ni++)
#pragma unroll
                for (int mi = 0; mi < 4; mi++) mma16816(acc[mi][ni], ahi[mi], bhi[ni]);
        }

        // issue chunk c+2 into the stage consumed at c-1 (safe: barrier above)
        if (c + 2 < nkb){
            const int ns = (stg + 2 >= NSTAGE) ? stg + 2 - NSTAGE : stg + 2;
            const uint32_t s = sbase + ns * STAGE_B;
            const __half* Ak = A + (c + 2) * 64;
            const __half* Bk = B + (c + 2) * 64;
#pragma unroll
            for (int i = 0; i < 4; i++) cpa16(s + smo[i], Ak + goA[i]);
#pragma unroll
            for (int i = 0; i < 4; i++) cpa16(s + TILE_B + smo[i], Bk + goB[i]);
            CP_COMMIT();
        }
        stg = (stg + 1 == NSTAGE) ? 0 : stg + 1;
    }
}

// ---------------- conversion kernels ----------------
__global__ __launch_bounds__(256) void k_cvt_x(const float* __restrict__ x){
    const int idx = blockIdx.x * 256 + threadIdx.x;
    const int m = idx / 192, kq = idx % 192;
    const int k = kq * 4;
    float4 v = *(const float4*)(x + (size_t)m * Cc + k);
    __half* p = g_xh + (size_t)m * Cc + k;
    uint2 u;
    u.x = h2u2(__float2half_rn(v.x), __float2half_rn(v.y));
    u.y = h2u2(__float2half_rn(v.z), __float2half_rn(v.w));
    *(uint2*)(p) = u;
}

__global__ __launch_bounds__(256) void k_cvt_w(
    const float* __restrict__ Wt, const float* __restrict__ bt,
    const float* __restrict__ Wp, const float* __restrict__ bp,
    const float* __restrict__ Wg, const float* __restrict__ bg)
{
    const int idx = blockIdx.x * 256 + threadIdx.x;
    const int n = idx / 192, kq = idx % 192;
    const int which = n / Dd, d = n % Dd;
    const int k = kq * 4;
    const float* W = (which == 0) ? Wt : (which == 1) ? Wp : Wg;
    __half h[4];
#pragma unroll
    for (int t = 0; t < 4; t++)
        h[t] = __float2half_rn(W[(size_t)(k + t) * Dd + d]);
    __half* p = g_wh + (size_t)n * Cc + k;
    uint2 u; u.x = h2u2(h[0], h[1]); u.y = h2u2(h[2], h[3]);
    *(uint2*)(p) = u;
    if (kq == 0){
        const float* bb = (which == 0) ? bt : (which == 1) ? bp : bg;
        g_bias[n] = bb[d];
    }
}

__global__ __launch_bounds__(256) void k_cvt_wo(const float* __restrict__ Wo){
    const int idx = blockIdx.x * 256 + threadIdx.x;
    const int n = idx / 96, kq = idx % 96;
    const int k = kq * 4;
    __half h[4];
#pragma unroll
    for (int t = 0; t < 4; t++)
        h[t] = __float2half_rn(Wo[(size_t)(k + t) * Cc + n]);
    __half* p = g_woh + (size_t)n * Dd + k;
    uint2 u; u.x = h2u2(h[0], h[1]); u.y = h2u2(h[2], h[3]);
    *(uint2*)(p) = u;
}

// ---------------- GEMM 1: projections ----------------
__global__ __launch_bounds__(256, 2) void k_proj_t(){
    extern __shared__ char sm[];
    const int lane = threadIdx.x & 31, w = threadIdx.x >> 5;
    const int wr = w >> 2, wc = w & 3;
    const int n0 = blockIdx.x * 128, m0 = blockIdx.y * 128;
    float acc[4][4][4];
    gemm1(g_xh + (size_t)m0 * Cc, Cc,
          g_wh + (size_t)n0 * Cc, Cc, Cc / 64, sm, acc);

    const int seg = n0 / Dd, d0 = n0 % Dd;
#pragma unroll
    for (int mi = 0; mi < 4; mi++)
#pragma unroll
    for (int ni = 0; ni < 4; ni++)
#pragma unroll
    for (int h = 0; h < 2; h++){
        const int r   = wr * 64 + mi * 16 + (lane >> 2) + h * 8;
        const int col = wc * 32 + ni * 8 + (lane & 3) * 2;
        const int mrow = m0 + r;
        const int ng = n0 + col;
        const float v0 = acc[mi][ni][h * 2]     + g_bias[ng];
        const float v1 = acc[mi][ni][h * 2 + 1] + g_bias[ng + 1];
        const __half h0 = __float2half_rn(v0), h1 = __float2half_rn(v1);
        const int d = d0 + col;
        if (seg == 0){
            *(uint32_t*)(g_th + (size_t)mrow * Dd + d) = h2u2(h0, h1);
        } else if (seg == 1){
            *(uint32_t*)(g_ph + (size_t)mrow * Dd + d) = h2u2(h0, h1);
        } else {
            const int b = mrow >> 10, ml = mrow & 1023;
            g_gh[(size_t)(b * Dd + d)     * Nn + ml] = h0;
            g_gh[(size_t)(b * Dd + d + 1) * Nn + ml] = h1;
        }
    }
}

// ---------------- GEMM 2: scores = (theta @ phi^T) * adj ----------------
__global__ __launch_bounds__(256, 2) void k_score_t(const float* __restrict__ adj){
    extern __shared__ char sm[];
    const int lane = threadIdx.x & 31, w = threadIdx.x >> 5;
    const int wr = w >> 2, wc = w & 3;
    const int b = blockIdx.z, j0 = blockIdx.x * 128, i0 = blockIdx.y * 128;
    float acc[4][4][4];
    gemm1(g_th + (size_t)(b * Nn + i0) * Dd, Dd,
          g_ph + (size_t)(b * Nn + j0) * Dd, Dd, Dd / 64, sm, acc);

#pragma unroll
    for (int mi = 0; mi < 4; mi++)
#pragma unroll
    for (int ni = 0; ni < 4; ni++)
#pragma unroll
    for (int h = 0; h < 2; h++){
        const int i = i0 + wr * 64 + mi * 16 + (lane >> 2) + h * 8;
        const int j = j0 + wc * 32 + ni * 8 + (lane & 3) * 2;
        const size_t idx = ((size_t)b * Nn + i) * Nn + j;
        const float2 a2 = *(const float2*)(adj + idx);
        float2 o;
        o.x = acc[mi][ni][h * 2]     * a2.x;
        o.y = acc[mi][ni][h * 2 + 1] * a2.y;
        *(float2*)(g_attn + idx) = o;
    }
}

// ---------------- softmax -> plain fp16 rows ----------------
__global__ __launch_bounds__(256) void k_softmax2(){
    const size_t row = blockIdx.x;
    const float4 v = ((const float4*)(g_attn + row * Nn))[threadIdx.x];

    float m = fmaxf(fmaxf(v.x, v.y), fmaxf(v.z, v.w));
#pragma unroll
    for (int o = 16; o; o >>= 1) m = fmaxf(m, __shfl_xor_sync(0xffffffffu, m, o));
    __shared__ float red[8];
    const int warp = threadIdx.x >> 5;
    if ((threadIdx.x & 31) == 0) red[warp] = m;
    __syncthreads();
    float bm = red[0];
#pragma unroll
    for (int i = 1; i < 8; i++) bm = fmaxf(bm, red[i]);
    __syncthreads();

    float4 e;
    e.x = __expf(v.x - bm); e.y = __expf(v.y - bm);
    e.z = __expf(v.z - bm); e.w = __expf(v.w - bm);
    float s = e.x + e.y + e.z + e.w;
#pragma unroll
    for (int o = 16; o; o >>= 1) s += __shfl_xor_sync(0xffffffffu, s, o);
    if ((threadIdx.x & 31) == 0) red[warp] = s;
    __syncthreads();
    float tot = red[0];
#pragma unroll
    for (int i = 1; i < 8; i++) tot += red[i];
    const float inv = 1.0f / tot;
    e.x *= inv; e.y *= inv; e.z *= inv; e.w *= inv;

    uint2 u;
    u.x = h2u2(__float2half_rn(e.x), __float2half_rn(e.y));
    u.y = h2u2(__float2half_rn(e.z), __float2half_rn(e.w));
    *(uint2*)(g_ath + row * Nn + threadIdx.x * 4) = u;
}

// ---------------- GEMM 3: attn @ g ----------------
__global__ __launch_bounds__(256, 2) void k_av_t(){
    extern __shared__ char sm[];
    const int lane = threadIdx.x & 31, w = threadIdx.x >> 5;
    const int wr = w >> 2, wc = w & 3;
    const int b = blockIdx.z, n0 = blockIdx.x * 128, i0 = blockIdx.y * 128;
    float acc[4][4][4];
    gemm1(g_ath + (size_t)(b * Nn + i0) * Nn, Nn,
          g_gh  + (size_t)(b * Dd + n0) * Nn, Nn, Nn / 64, sm, acc);

#pragma unroll
    for (int mi = 0; mi < 4; mi++)
#pragma unroll
    for (int ni = 0; ni < 4; ni++)
#pragma unroll
    for (int h = 0; h < 2; h++){
        const int r   = wr * 64 + mi * 16 + (lane >> 2) + h * 8;
        const int col = wc * 32 + ni * 8 + (lane & 3) * 2;
        const int mrow = b * Nn + i0 + r;
        const __half h0 = __float2half_rn(acc[mi][ni][h * 2]);
        const __half h1 = __float2half_rn(acc[mi][ni][h * 2 + 1]);
        *(uint32_t*)(g_odh + (size_t)mrow * Dd + n0 + col) = h2u2(h0, h1);
    }
}

// ---------------- GEMM 4: output + bias + residual ----------------
__global__ __launch_bounds__(256, 2) void k_out_t(
    const float* __restrict__ x, const float* __restrict__ bo, float* __restrict__ out)
{
    extern __shared__ char sm[];
    const int lane = threadIdx.x & 31, w = threadIdx.x >> 5;
    const int wr = w >> 2, wc = w & 3;
    const int n0 = blockIdx.x * 128, m0 = blockIdx.y * 128;
    float acc[4][4][4];
    gemm1(g_odh + (size_t)m0 * Dd, Dd,
          g_woh + (size_t)n0 * Dd, Dd, Dd / 64, sm, acc);

#pragma unroll
    for (int mi = 0; mi < 4; mi++)
#pragma unroll
    for (int ni = 0; ni < 4; ni++)
#pragma unroll
    for (int h = 0; h < 2; h++){
        const int row = m0 + wr * 64 + mi * 16 + (lane >> 2) + h * 8;
        const int cg  = n0 + wc * 32 + ni * 8 + (lane & 3) * 2;
        const size_t idx = (size_t)row * Cc + cg;
        const float2 xv = *(const float2*)(x + idx);
        const float2 bv = *(const float2*)(bo + cg);
        float2 o;
        o.x = acc[mi][ni][h * 2]     + bv.x + xv.x;
        o.y = acc[mi][ni][h * 2 + 1] + bv.y + xv.y;
        *(float2*)(out + idx) = o;
    }
}

// ---------------------------------------------------------------------------
extern "C" void kernel_launch(void* const* d_in, const int* in_sizes, int n_in,
                              void* d_out, int out_size)
{
    const float* x  = (const float*)d_in[0];
    const float* adj = (const float*)d_in[1];
    const float* Wt = (const float*)d_in[2];
    const float* bt = (const float*)d_in[3];
    const float* Wp = (const float*)d_in[4];
    const float* bp = (const float*)d_in[5];
    const float* Wg = (const float*)d_in[6];
    const float* bg = (const float*)d_in[7];
    const float* Wo = (const float*)d_in[8];
    const float* bo = (const float*)d_in[9];
    float* out = (float*)d_out;

    static bool attr_done = false;
    if (!attr_done){
        cudaFuncSetAttribute(k_proj_t,  cudaFuncAttributeMaxDynamicSharedMemorySize, SMEM_DYN);
        cudaFuncSetAttribute(k_score_t, cudaFuncAttributeMaxDynamicSharedMemorySize, SMEM_DYN);
        cudaFuncSetAttribute(k_av_t,    cudaFuncAttributeMaxDynamicSharedMemorySize, SMEM_DYN);
        cudaFuncSetAttribute(k_out_t,   cudaFuncAttributeMaxDynamicSharedMemorySize, SMEM_DYN);
        attr_done = true;
    }

    k_cvt_x <<<(Bz * Nn * 192) / 256, 256>>>(x);
    k_cvt_w <<<(3 * Dd * 192) / 256, 256>>>(Wt, bt, Wp, bp, Wg, bg);
    k_cvt_wo<<<(Cc * 96) / 256, 256>>>(Wo);

    k_proj_t <<<dim3(9, 128),   256, SMEM_DYN>>>();
    k_score_t<<<dim3(8, 8, Bz), 256, SMEM_DYN>>>(adj);
    k_softmax2<<<Bz * Nn, 256>>>();
    k_av_t   <<<dim3(3, 8, Bz), 256, SMEM_DYN>>>();
    k_out_t  <<<dim3(6, 128),   256, SMEM_DYN>>>(x, bo, out);
}

// round 15
// speedup vs baseline: 2.3176x; 1.0625x over previous
#include <cuda_runtime.h>
#include <cuda_fp16.h>
#include <cstdint>

#define Bz 16
#define Nn 1024
#define Cc 768
#define Dd 384

#define TILE_B  16384            // 128 rows x 128B (64 fp16 k-elems per row)
#define STAGE_B 32768            // A tile + B tile
#define NSTAGE  3
#define SMEM_DYN (NSTAGE*STAGE_B + 128)

// ---------------- static scratch (plain fp16, LD = K) ----------------
__device__ __align__(16) __half g_xh [(size_t)Bz*Nn*Cc];     // A in proj
__device__ __align__(16) __half g_wh [(size_t)3*Dd*Cc];      // B in proj (row n, col k)
__device__              float   g_bias[3*Dd];
__device__ __align__(16) __half g_th [(size_t)Bz*Nn*Dd];     // A in score
__device__ __align__(16) __half g_ph [(size_t)Bz*Nn*Dd];     // B in score
__device__ __align__(16) __half g_gh [(size_t)Bz*Dd*Nn];     // B in av (row d, col token)
__device__ __align__(16) float  g_attn[(size_t)Bz*Nn*Nn];
__device__ __align__(16) __half g_ath[(size_t)Bz*Nn*Nn];     // A in av (softmax rows)
__device__ __align__(16) __half g_odh[(size_t)Bz*Nn*Dd];     // A in out
__device__ __align__(16) __half g_woh[(size_t)Cc*Dd];        // B in out

// ---------------- helpers ----------------
__device__ __forceinline__ uint32_t smem_u32(const void* p){
    uint32_t a;
    asm("{ .reg .u64 t; cvta.to.shared.u64 t, %1; cvt.u32.u64 %0, t; }" : "=r"(a) : "l"(p));
    return a;
}
__device__ __forceinline__ void cpa16(uint32_t dst, const void* src){
    asm volatile("cp.async.cg.shared.global [%0], [%1], 16;" :: "r"(dst), "l"(src));
}
#define CP_COMMIT() asm volatile("cp.async.commit_group;" ::: "memory")
#define CP_WAIT(N)  asm volatile("cp.async.wait_group %0;" :: "n"(N) : "memory")

__device__ __forceinline__ void ldsm4(uint32_t (&d)[4], uint32_t a){
    asm volatile("ldmatrix.sync.aligned.m8n8.x4.shared.b16 {%0,%1,%2,%3}, [%4];"
        : "=r"(d[0]), "=r"(d[1]), "=r"(d[2]), "=r"(d[3]) : "r"(a));
}
__device__ __forceinline__ void mma16816(float (&c)[4], const uint32_t (&a)[4],
                                         uint32_t b0, uint32_t b1){
    asm volatile("mma.sync.aligned.m16n8k16.row.col.f32.f16.f16.f32 "
        "{%0,%1,%2,%3}, {%4,%5,%6,%7}, {%8,%9}, {%0,%1,%2,%3};"
        : "+f"(c[0]), "+f"(c[1]), "+f"(c[2]), "+f"(c[3])
        : "r"(a[0]), "r"(a[1]), "r"(a[2]), "r"(a[3]), "r"(b0), "r"(b1));
}

__device__ __forceinline__ uint32_t h2u2(__half a, __half b){
    return (uint32_t)__half_as_ushort(a) | ((uint32_t)__half_as_ushort(b) << 16);
}

// ---------------- pure fp16 HMMA GEMM core ----------------
// Chunk = 64 k (128B rows). CTA tile 128x128, 8 warps (2x4), warp tile 64x32.
// R14: B fragments via 2x ldsm4 per ks (mapping validated in R10 run).
__device__ __forceinline__ void gemm1(
    const __half* __restrict__ A, int ldA,
    const __half* __restrict__ B, int ldB,
    int nkb, char* sm, float acc[4][4][4])
{
    const int tid  = threadIdx.x;
    const int lane = tid & 31;
    const int w    = tid >> 5;
    const int wr   = w >> 2, wc = w & 3;
    const uint32_t sbase = (smem_u32(sm) + 127u) & ~127u;

    int goA[4], goB[4], smo[4];
#pragma unroll
    for (int i = 0; i < 4; i++){
        int idx = i * 256 + tid;
        int rr = idx >> 3, cc = idx & 7;
        goA[i] = rr * ldA + cc * 8;
        goB[i] = rr * ldB + cc * 8;
        smo[i] = rr * 128 + ((cc * 16) ^ ((rr & 7) << 4));
    }

    const int xorv = (lane & 7) << 4;
    int arow[4];
#pragma unroll
    for (int mi = 0; mi < 4; mi++) arow[mi] = (wr * 64 + mi * 16 + (lane & 15)) * 128;
    // B ldsm4 lane map: lanes 0-7 rows +0..7 khalf0; 8-15 rows +0..7 khalf1;
    //                   16-23 rows +8..15 khalf0; 24-31 rows +8..15 khalf1
    const int brow4 = (wc * 32 + ((lane >> 4) << 3) + (lane & 7)) * 128;
    const int acs = (lane & 16);
    const int bcs = (lane & 8) << 1;

#pragma unroll
    for (int mi = 0; mi < 4; mi++)
#pragma unroll
        for (int ni = 0; ni < 4; ni++)
#pragma unroll
            for (int q = 0; q < 4; q++) acc[mi][ni][q] = 0.f;

    // prologue: issue chunks 0,1
#pragma unroll
    for (int pc = 0; pc < 2; pc++){
        const uint32_t s = sbase + pc * STAGE_B;
        const __half* Ak = A + pc * 64;
        const __half* Bk = B + pc * 64;
#pragma unroll
        for (int i = 0; i < 4; i++) cpa16(s + smo[i], Ak + goA[i]);
#pragma unroll
        for (int i = 0; i < 4; i++) cpa16(s + TILE_B + smo[i], Bk + goB[i]);
        CP_COMMIT();
    }

    int stg = 0;
    for (int c = 0; c < nkb; ++c){
        if (c + 1 < nkb) { CP_WAIT(1); } else { CP_WAIT(0); }
        __syncthreads();

        const uint32_t sA = sbase + stg * STAGE_B;
        const uint32_t sB = sA + TILE_B;
#pragma unroll
        for (int ks = 0; ks < 4; ks++){
            const int chA = ((ks << 5) | acs);
            const int chB = ((ks << 5) | bcs);
            uint32_t ahi[4][4], bh[2][4];
#pragma unroll
            for (int p = 0; p < 2; p++)
                ldsm4(bh[p], sB + brow4 + p * 2048 + (chB ^ xorv));
#pragma unroll
            for (int mi = 0; mi < 4; mi++)
                ldsm4(ahi[mi], sA + arow[mi] + (chA ^ xorv));
#pragma unroll
            for (int ni = 0; ni < 4; ni++)
#pragma unroll
                for (int mi = 0; mi < 4; mi++)
                    mma16816(acc[mi][ni], ahi[mi],
                             bh[ni >> 1][(ni & 1) * 2], bh[ni >> 1][(ni & 1) * 2 + 1]);
        }

        // issue chunk c+2 into the stage consumed at c-1 (safe: barrier above)
        if (c + 2 < nkb){
            const int ns = (stg + 2 >= NSTAGE) ? stg + 2 - NSTAGE : stg + 2;
            const uint32_t s = sbase + ns * STAGE_B;
            const __half* Ak = A + (c + 2) * 64;
            const __half* Bk = B + (c + 2) * 64;
#pragma unroll
            for (int i = 0; i < 4; i++) cpa16(s + smo[i], Ak + goA[i]);
#pragma unroll
            for (int i = 0; i < 4; i++) cpa16(s + TILE_B + smo[i], Bk + goB[i]);
            CP_COMMIT();
        }
        stg = (stg + 1 == NSTAGE) ? 0 : stg + 1;
    }
}

// ---------------- merged conversion kernel ----------------
// blocks [0, 12288): x      (16384 rows x 192 quads)
// blocks [12288, 13152): W  (1152 rows x 192 quads)
// blocks [13152, 13440): Wo (768 rows x 96 quads)
#define CVT_XB 12288
#define CVT_WB 864
#define CVT_OB 288
__global__ __launch_bounds__(256) void k_cvt_all(
    const float* __restrict__ x,
    const float* __restrict__ Wt, const float* __restrict__ bt,
    const float* __restrict__ Wp, const float* __restrict__ bp,
    const float* __restrict__ Wg, const float* __restrict__ bg,
    const float* __restrict__ Wo)
{
    const int blk = blockIdx.x;
    if (blk < CVT_XB){
        const int idx = blk * 256 + threadIdx.x;
        const int m = idx / 192, kq = idx % 192;
        const int k = kq * 4;
        float4 v = *(const float4*)(x + (size_t)m * Cc + k);
        uint2 u;
        u.x = h2u2(__float2half_rn(v.x), __float2half_rn(v.y));
        u.y = h2u2(__float2half_rn(v.z), __float2half_rn(v.w));
        *(uint2*)(g_xh + (size_t)m * Cc + k) = u;
    } else if (blk < CVT_XB + CVT_WB){
        const int idx = (blk - CVT_XB) * 256 + threadIdx.x;
        const int n = idx / 192, kq = idx % 192;
        const int which = n / Dd, d = n % Dd;
        const int k = kq * 4;
        const float* W = (which == 0) ? Wt : (which == 1) ? Wp : Wg;
        __half h[4];
#pragma unroll
        for (int t = 0; t < 4; t++)
            h[t] = __float2half_rn(W[(size_t)(k + t) * Dd + d]);
        uint2 u; u.x = h2u2(h[0], h[1]); u.y = h2u2(h[2], h[3]);
        *(uint2*)(g_wh + (size_t)n * Cc + k) = u;
        if (kq == 0){
            const float* bb = (which == 0) ? bt : (which == 1) ? bp : bg;
            g_bias[n] = bb[d];
        }
    } else {
        const int idx = (blk - CVT_XB - CVT_WB) * 256 + threadIdx.x;
        const int n = idx / 96, kq = idx % 96;
        const int k = kq * 4;
        __half h[4];
#pragma unroll
        for (int t = 0; t < 4; t++)
            h[t] = __float2half_rn(Wo[(size_t)(k + t) * Cc + n]);
        uint2 u; u.x = h2u2(h[0], h[1]); u.y = h2u2(h[2], h[3]);
        *(uint2*)(g_woh + (size_t)n * Dd + k) = u;
    }
}

// ---------------- GEMM 1: projections ----------------
__global__ __launch_bounds__(256, 2) void k_proj_t(){
    extern __shared__ char sm[];
    const int lane = threadIdx.x & 31, w = threadIdx.x >> 5;
    const int wr = w >> 2, wc = w & 3;
    const int n0 = blockIdx.x * 128, m0 = blockIdx.y * 128;
    float acc[4][4][4];
    gemm1(g_xh + (size_t)m0 * Cc, Cc,
          g_wh + (size_t)n0 * Cc, Cc, Cc / 64, sm, acc);

    const int seg = n0 / Dd, d0 = n0 % Dd;
#pragma unroll
    for (int mi = 0; mi < 4; mi++)
#pragma unroll
    for (int ni = 0; ni < 4; ni++)
#pragma unroll
    for (int h = 0; h < 2; h++){
        const int r   = wr * 64 + mi * 16 + (lane >> 2) + h * 8;
        const int col = wc * 32 + ni * 8 + (lane & 3) * 2;
        const int mrow = m0 + r;
        const int ng = n0 + col;
        const float v0 = acc[mi][ni][h * 2]     + g_bias[ng];
        const float v1 = acc[mi][ni][h * 2 + 1] + g_bias[ng + 1];
        const __half h0 = __float2half_rn(v0), h1 = __float2half_rn(v1);
        const int d = d0 + col;
        if (seg == 0){
            *(uint32_t*)(g_th + (size_t)mrow * Dd + d) = h2u2(h0, h1);
        } else if (seg == 1){
            *(uint32_t*)(g_ph + (size_t)mrow * Dd + d) = h2u2(h0, h1);
        } else {
            const int b = mrow >> 10, ml = mrow & 1023;
            g_gh[(size_t)(b * Dd + d)     * Nn + ml] = h0;
            g_gh[(size_t)(b * Dd + d + 1) * Nn + ml] = h1;
        }
    }
}

// ---------------- GEMM 2: scores = (theta @ phi^T) * adj ----------------
__global__ __launch_bounds__(256, 2) void k_score_t(const float* __restrict__ adj){
    extern __shared__ char sm[];
    const int lane = threadIdx.x & 31, w = threadIdx.x >> 5;
    const int wr = w >> 2, wc = w & 3;
    const int b = blockIdx.z, j0 = blockIdx.x * 128, i0 = blockIdx.y * 128;
    float acc[4][4][4];
    gemm1(g_th + (size_t)(b * Nn + i0) * Dd, Dd,
          g_ph + (size_t)(b * Nn + j0) * Dd, Dd, Dd / 64, sm, acc);

#pragma unroll
    for (int mi = 0; mi < 4; mi++)
#pragma unroll
    for (int ni = 0; ni < 4; ni++)
#pragma unroll
    for (int h = 0; h < 2; h++){
        const int i = i0 + wr * 64 + mi * 16 + (lane >> 2) + h * 8;
        const int j = j0 + wc * 32 + ni * 8 + (lane & 3) * 2;
        const size_t idx = ((size_t)b * Nn + i) * Nn + j;
        const float2 a2 = *(const float2*)(adj + idx);
        float2 o;
        o.x = acc[mi][ni][h * 2]     * a2.x;
        o.y = acc[mi][ni][h * 2 + 1] * a2.y;
        *(float2*)(g_attn + idx) = o;
    }
}

// ---------------- softmax -> plain fp16 rows ----------------
// 4 rows per 256-thread block; 64 threads per row; 4 float4 per thread (MLP=4).
__global__ __launch_bounds__(256) void k_softmax2(){
    const int slot = threadIdx.x >> 6;          // 0..3 row within block
    const int t    = threadIdx.x & 63;          // 0..63 thread within row
    const size_t row = (size_t)blockIdx.x * 4 + slot;
    const float4* p = (const float4*)(g_attn + row * Nn);

    float4 v[4];
#pragma unroll
    for (int q = 0; q < 4; q++) v[q] = p[t + q * 64];

    float m = -1e30f;
#pragma unroll
    for (int q = 0; q < 4; q++)
        m = fmaxf(m, fmaxf(fmaxf(v[q].x, v[q].y), fmaxf(v[q].z, v[q].w)));
#pragma unroll
    for (int o = 16; o; o >>= 1) m = fmaxf(m, __shfl_xor_sync(0xffffffffu, m, o));
    __shared__ float red[8];
    const int wid = threadIdx.x >> 5;           // 0..7; row uses warps 2*slot, 2*slot+1
    if ((threadIdx.x & 31) == 0) red[wid] = m;
    __syncthreads();
    const float bm = fmaxf(red[slot * 2], red[slot * 2 + 1]);
    __syncthreads();

    float s = 0.f;
#pragma unroll
    for (int q = 0; q < 4; q++){
        v[q].x = __expf(v[q].x - bm); v[q].y = __expf(v[q].y - bm);
        v[q].z = __expf(v[q].z - bm); v[q].w = __expf(v[q].w - bm);
        s += (v[q].x + v[q].y) + (v[q].z + v[q].w);
    }
#pragma unroll
    for (int o = 16; o; o >>= 1) s += __shfl_xor_sync(0xffffffffu, s, o);
    if ((threadIdx.x & 31) == 0) red[wid] = s;
    __syncthreads();
    const float inv = 1.0f / (red[slot * 2] + red[slot * 2 + 1]);

    __half* dst = g_ath + row * Nn;
#pragma unroll
    for (int q = 0; q < 4; q++){
        uint2 u;
        u.x = h2u2(__float2half_rn(v[q].x * inv), __float2half_rn(v[q].y * inv));
        u.y = h2u2(__float2half_rn(v[q].z * inv), __float2half_rn(v[q].w * inv));
        *(uint2*)(dst + (t + q * 64) * 4) = u;
    }
}

// ---------------- GEMM 3: attn @ g ----------------
__global__ __launch_bounds__(256, 2) void k_av_t(){
    extern __shared__ char sm[];
    const int lane = threadIdx.x & 31, w = threadIdx.x >> 5;
    const int wr = w >> 2, wc = w & 3;
    const int b = blockIdx.z, n0 = blockIdx.x * 128, i0 = blockIdx.y * 128;
    float acc[4][4][4];
    gemm1(g_ath + (size_t)(b * Nn + i0) * Nn, Nn,
          g_gh  + (size_t)(b * Dd + n0) * Nn, Nn, Nn / 64, sm, acc);

#pragma unroll
    for (int mi = 0; mi < 4; mi++)
#pragma unroll
    for (int ni = 0; ni < 4; ni++)
#pragma unroll
    for (int h = 0; h < 2; h++){
        const int r   = wr * 64 + mi * 16 + (lane >> 2) + h * 8;
        const int col = wc * 32 + ni * 8 + (lane & 3) * 2;
        const int mrow = b * Nn + i0 + r;
        const __half h0 = __float2half_rn(acc[mi][ni][h * 2]);
        const __half h1 = __float2half_rn(acc[mi][ni][h * 2 + 1]);
        *(uint32_t*)(g_odh + (size_t)mrow * Dd + n0 + col) = h2u2(h0, h1);
    }
}

// ---------------- GEMM 4: output + bias + residual ----------------
__global__ __launch_bounds__(256, 2) void k_out_t(
    const float* __restrict__ x, const float* __restrict__ bo, float* __restrict__ out)
{
    extern __shared__ char sm[];
    const int lane = threadIdx.x & 31, w = threadIdx.x >> 5;
    const int wr = w >> 2, wc = w & 3;
    const int n0 = blockIdx.x * 128, m0 = blockIdx.y * 128;
    float acc[4][4][4];
    gemm1(g_odh + (size_t)m0 * Dd, Dd,
          g_woh + (size_t)n0 * Dd, Dd, Dd / 64, sm, acc);

#pragma unroll
    for (int mi = 0; mi < 4; mi++)
#pragma unroll
    for (int ni = 0; ni < 4; ni++)
#pragma unroll
    for (int h = 0; h < 2; h++){
        const int row = m0 + wr * 64 + mi * 16 + (lane >> 2) + h * 8;
        const int cg  = n0 + wc * 32 + ni * 8 + (lane & 3) * 2;
        const size_t idx = (size_t)row * Cc + cg;
        const float2 xv = *(const float2*)(x + idx);
        const float2 bv = *(const float2*)(bo + cg);
        float2 o;
        o.x = acc[mi][ni][h * 2]     + bv.x + xv.x;
        o.y = acc[mi][ni][h * 2 + 1] + bv.y + xv.y;
        *(float2*)(out + idx) = o;
    }
}

// ---------------------------------------------------------------------------
extern "C" void kernel_launch(void* const* d_in, const int* in_sizes, int n_in,
                              void* d_out, int out_size)
{
    const float* x  = (const float*)d_in[0];
    const float* adj = (const float*)d_in[1];
    const float* Wt = (const float*)d_in[2];
    const float* bt = (const float*)d_in[3];
    const float* Wp = (const float*)d_in[4];
    const float* bp = (const float*)d_in[5];
    const float* Wg = (const float*)d_in[6];
    const float* bg = (const float*)d_in[7];
    const float* Wo = (const float*)d_in[8];
    const float* bo = (const float*)d_in[9];
    float* out = (float*)d_out;

    static bool attr_done = false;
    if (!attr_done){
        cudaFuncSetAttribute(k_proj_t,  cudaFuncAttributeMaxDynamicSharedMemorySize, SMEM_DYN);
        cudaFuncSetAttribute(k_score_t, cudaFuncAttributeMaxDynamicSharedMemorySize, SMEM_DYN);
        cudaFuncSetAttribute(k_av_t,    cudaFuncAttributeMaxDynamicSharedMemorySize, SMEM_DYN);
        cudaFuncSetAttribute(k_out_t,   cudaFuncAttributeMaxDynamicSharedMemorySize, SMEM_DYN);
        attr_done = true;
    }

    k_cvt_all<<<CVT_XB + CVT_WB + CVT_OB, 256>>>(x, Wt, bt, Wp, bp, Wg, bg, Wo);

    k_proj_t <<<dim3(9, 128),   256, SMEM_DYN>>>();
    k_score_t<<<dim3(8, 8, Bz), 256, SMEM_DYN>>>(adj);
    k_softmax2<<<(Bz * Nn) / 4, 256>>>();
    k_av_t   <<<dim3(3, 8, Bz), 256, SMEM_DYN>>>();
    k_out_t  <<<dim3(6, 128),   256, SMEM_DYN>>>(x, bo, out);
}